// round 13
// baseline (speedup 1.0000x reference)
#include <cuda_runtime.h>
#include <cuda_bf16.h>
#include <cstdint>

// ---------------- problem constants ----------------
#define BQ   4
#define DQ   64
#define HQ   64
#define WQ   64
#define HWQ  4096
#define SQ   64
#define NQ   8192
#define KQ   4
#define D9   576
#define HID  256
#define NPIX 16384        // B*HWQ distinct pixel rows
#define ATTR 65536        // attention MLP rows: B*HWQ*4
#define NR2  196608       // ATTR + B*NQ*4 local rows
#define NCHUNK 128

typedef unsigned short ushortt;

// ---------------- device scratch ----------------
__device__ int      g_segm[BQ * HWQ];
__device__ float    g_partv[BQ * NCHUNK * SQ * KQ];
__device__ int      g_parti[BQ * NCHUNK * SQ * KQ];
__device__ float    g_top4v[BQ * SQ * KQ];
__device__ int      g_top4i[BQ * SQ * KQ];
__device__ uint32_t g_W0f32[D9 * HID];                  // packed (hi|lo<<16) bf16
__device__ uint32_t g_Wp32[3 * HID * HID];              // w1..w3 packed [k][n]
__device__ __align__(16) float    g_T[(size_t)NPIX * HID];   // 16.8MB
__device__ uint32_t g_H1[(size_t)NR2 * HID];            // packed hidden activations
__device__ uint32_t g_H2[(size_t)NR2 * HID];
__device__ int      g_rowsrc[NR2];                      // T-row index per MLP row
__device__ float    g_tail[(size_t)NR2 * 4];
__device__ float    g_rwt[NR2];                         // per-row ensemble weight
__device__ int      g_qpc[BQ * NQ];                     // query -> (b*4096+pc1d)
__device__ float    g_wp[2 * (size_t)NR2 * 3];          // per-row weighted pred (2 halves)

// ---------------- helpers ----------------
__device__ __forceinline__ ushortt f2b(float x) {
    return __bfloat16_as_ushort(__float2bfloat16_rn(x));
}
__device__ __forceinline__ float b2f(ushortt u) {
    return __bfloat162float(__ushort_as_bfloat16(u));
}
__device__ __forceinline__ uint32_t packsplit(float v) {
    ushortt h = f2b(v);
    ushortt l = f2b(v - b2f(h));
    return (uint32_t)h | ((uint32_t)l << 16);
}
__device__ __forceinline__ uint32_t smem_u32(const void* p) {
    uint32_t a;
    asm("{ .reg .u64 t; cvta.to.shared.u64 t, %1; cvt.u32.u64 %0, t; }" : "=r"(a) : "l"(p));
    return a;
}
__device__ __forceinline__ void mma_bf16(float* c, const unsigned* a,
                                         unsigned b0, unsigned b1) {
    asm volatile(
        "mma.sync.aligned.m16n8k16.row.col.f32.bf16.bf16.f32 "
        "{%0,%1,%2,%3},{%4,%5,%6,%7},{%8,%9},{%0,%1,%2,%3};\n"
        : "+f"(c[0]), "+f"(c[1]), "+f"(c[2]), "+f"(c[3])
        : "r"(a[0]), "r"(a[1]), "r"(a[2]), "r"(a[3]), "r"(b0), "r"(b1));
}
__device__ __forceinline__ void ldm4(unsigned& r0, unsigned& r1, unsigned& r2,
                                     unsigned& r3, uint32_t addr) {
    asm volatile("ldmatrix.sync.aligned.m8n8.x4.shared.b16 {%0,%1,%2,%3}, [%4];"
                 : "=r"(r0), "=r"(r1), "=r"(r2), "=r"(r3) : "r"(addr));
}
// top-4 insertion, lax.top_k tie semantics
__device__ __forceinline__ void ins4(float v[4], int id[4], float val, int p) {
    if (!(val > v[3] || (val == v[3] && p < id[3]))) return;
    int pos = 3;
    while (pos > 0 && (val > v[pos - 1] || (val == v[pos - 1] && p < id[pos - 1]))) pos--;
    for (int q = 3; q > pos; q--) { v[q] = v[q - 1]; id[q] = id[q - 1]; }
    v[pos] = val; id[pos] = p;
}

// ---------------- prep ----------------
__global__ void k_prepw(const float* __restrict__ w0, const float* __restrict__ w1,
                        const float* __restrict__ w2, const float* __restrict__ w3) {
    int t = blockIdx.x * blockDim.x + threadIdx.x;
    const int n0 = D9 * HID;
    if (t < n0) {
        g_W0f32[t] = packsplit(w0[t]);
        return;
    }
    int t2 = t - n0;
    if (t2 >= 3 * HID * HID) return;
    int layer = t2 / (HID * HID);
    int i = t2 % (HID * HID);
    const float* w = (layer == 0) ? w1 : (layer == 1) ? w2 : w3;
    g_Wp32[t2] = packsplit(w[i]);
}

// ---------------- argmax ----------------
__global__ void k_argmax(const float* __restrict__ attn) {
    int t = blockIdx.x * blockDim.x + threadIdx.x;
    if (t >= BQ * HWQ) return;
    const float* row = attn + (size_t)t * SQ;
    float best = row[0]; int bi = 0;
    for (int s = 1; s < SQ; s++) {
        float v = row[s];
        if (v > best) { best = v; bi = s; }
    }
    g_segm[t] = bi;
}

// ---------------- top4 stage A ----------------
__global__ void k_top4a(const float* __restrict__ attn) {
    __shared__ float tile[32][SQ + 1];
    __shared__ float sv[4][SQ][4];
    __shared__ int   si[4][SQ][4];
    int b = blockIdx.x >> 7;
    int chunk = blockIdx.x & 127;
    int tid = threadIdx.x;
    int s = tid & 63, sub = tid >> 6;
    int p0 = chunk * 32;
    for (int i = tid; i < 32 * SQ; i += 256) {
        int r = i >> 6, c = i & 63;
        tile[r][c] = attn[((size_t)(b * HWQ) + p0 + r) * SQ + c];
    }
    __syncthreads();
    float v[4]  = {-1e30f, -1e30f, -1e30f, -1e30f};
    int   id[4] = {0x7fffffff, 0x7fffffff, 0x7fffffff, 0x7fffffff};
    for (int rr = 0; rr < 8; rr++) {
        int r = sub * 8 + rr;
        ins4(v, id, tile[r][s], p0 + r);
    }
    for (int q = 0; q < 4; q++) { sv[sub][s][q] = v[q]; si[sub][s][q] = id[q]; }
    __syncthreads();
    if (sub == 0) {
        float fv[4]  = {-1e30f, -1e30f, -1e30f, -1e30f};
        int   fi[4]  = {0x7fffffff, 0x7fffffff, 0x7fffffff, 0x7fffffff};
        for (int ss = 0; ss < 4; ss++)
            for (int q = 0; q < 4; q++)
                ins4(fv, fi, sv[ss][s][q], si[ss][s][q]);
        int base = ((b * NCHUNK + chunk) * SQ + s) * 4;
        for (int q = 0; q < 4; q++) { g_partv[base + q] = fv[q]; g_parti[base + q] = fi[q]; }
    }
}

// ---------------- top4 stage B ----------------
__global__ void k_top4b() {
    int t = threadIdx.x;
    int b = t >> 6, s = t & 63;
    float v[4]  = {-1e30f, -1e30f, -1e30f, -1e30f};
    int   id[4] = {0x7fffffff, 0x7fffffff, 0x7fffffff, 0x7fffffff};
    for (int ch = 0; ch < NCHUNK; ch++) {
        int base = ((b * NCHUNK + ch) * SQ + s) * 4;
        for (int q = 0; q < 4; q++) ins4(v, id, g_partv[base + q], g_parti[base + q]);
    }
    int o = (b * SQ + s) * 4;
    for (int q = 0; q < 4; q++) { g_top4v[o + q] = v[q]; g_top4i[o + q] = id[q]; }
}

// ---------------- build ----------------
__global__ void k_build(const float* __restrict__ coord,
                        const float* __restrict__ cell) {
    int t = blockIdx.x * blockDim.x + threadIdx.x;
    if (t < BQ * HWQ) {
        int b = t >> 12;          // HWQ = 4096
        int pc1d = t & 4095;
        int segm = g_segm[b * HWQ + pc1d];
        const float* tv = &g_top4v[(b * SQ + segm) * 4];
        const int*   ti = &g_top4i[(b * SQ + segm) * 4];
        float sum = tv[0] + tv[1] + tv[2] + tv[3];
        size_t cb = (size_t)b * NQ * 2;   // cell uniform per batch
        float rc0 = cell[cb] * (float)HQ, rc1 = cell[cb + 1] * (float)WQ;
        for (int k = 0; k < 4; k++) {
            int rc = ti[k];
            int rrc = rc - pc1d;
            float rel0 = (float)(rrc >> 6) * (1.0f / (float)HQ);
            float rel1 = (float)(rrc & 63) * (1.0f / (float)WQ);
            int rowr = t * 4 + k;
            g_rowsrc[rowr] = rc;             // batch-0 row of T (faithful)
            g_tail[(size_t)rowr * 4 + 0] = rel0;
            g_tail[(size_t)rowr * 4 + 1] = rel1;
            g_tail[(size_t)rowr * 4 + 2] = rc0;
            g_tail[(size_t)rowr * 4 + 3] = rc1;
            g_rwt[rowr] = tv[k] / sum;
        }
        return;
    }
    int q = t - BQ * HWQ;
    if (q >= BQ * NQ) return;
    int b = q >> 13;
    size_t cb = (size_t)q * 2;
    float c0 = coord[cb], c1 = coord[cb + 1];
    float rc0 = cell[cb] * (float)HQ, rc1 = cell[cb + 1] * (float)WQ;

    float pcf0 = (c0 + 1.0f) / 2.0f * (float)HQ;
    float pcf1 = (c1 + 1.0f) / 2.0f * (float)WQ;
    int pc0 = (int)pcf0; pc0 = max(0, min(HWQ - 1, pc0));
    int pc1 = (int)pcf1; pc1 = max(0, min(HWQ - 1, pc1));
    int pc1d = pc0 * HQ + pc1;
    pc1d = max(0, min(HWQ - 1, pc1d));
    g_qpc[q] = b * HWQ + pc1d;

    const float offv[4][2] = {{-1.f, -1.f}, {-1.f, 1.f}, {1.f, -1.f}, {1.f, 1.f}};
    float area[4];
    for (int j = 0; j < 4; j++) {
        float rx = 1.0f / (float)HQ, ry = 1.0f / (float)WQ;
        float cc0 = c0 + offv[j][0] * rx + 1e-6f;
        float cc1 = c1 + offv[j][1] * ry + 1e-6f;
        cc0 = fminf(fmaxf(cc0, -1.0f + 1e-6f), 1.0f - 1e-6f);
        cc1 = fminf(fmaxf(cc1, -1.0f + 1e-6f), 1.0f - 1e-6f);
        float fy = ((cc0 + 1.0f) * (float)HQ - 1.0f) / 2.0f;
        float fx = ((cc1 + 1.0f) * (float)WQ - 1.0f) / 2.0f;
        int iy = (int)rintf(fy); iy = max(0, min(HQ - 1, iy));
        int ix = (int)rintf(fx); ix = max(0, min(WQ - 1, ix));
        int flat = iy * WQ + ix;
        float qc0 = -1.0f + (2.0f * (float)iy + 1.0f) / (float)HQ;
        float qc1 = -1.0f + (2.0f * (float)ix + 1.0f) / (float)WQ;
        float r0 = (c0 - qc0) * (float)HQ;
        float r1 = (c1 - qc1) * (float)WQ;
        int rowr = ATTR + q * 4 + j;
        g_rowsrc[rowr] = b * HWQ + flat;
        g_tail[(size_t)rowr * 4 + 0] = r0;
        g_tail[(size_t)rowr * 4 + 1] = r1;
        g_tail[(size_t)rowr * 4 + 2] = rc0;
        g_tail[(size_t)rowr * 4 + 3] = rc1;
        area[j] = fabsf(r0 * r1) + 1e-9f;
    }
    float tot = area[0] + area[1] + area[2] + area[3];
    for (int j = 0; j < 4; j++) g_rwt[ATTR + q * 4 + j] = area[3 - j] / tot;
}

// ---------------- GEMM: BM=64 BN=128 BK=16, 3 CTAs/SM, ldmatrix ----------------
// per buffer (bytes): AH 0 (64x48=3072), AL 3072, BH 6144 (128x48), BL 12288
//   -> buffer = 18432; two buffers 36864; sw0t @36864 (4KB); total 40960
#define GB_BUF 18432u
#define GB_AL  3072u
#define GB_BH  6144u
#define GB_BL  12288u
#define GB_W0T 36864u
#define GSM_TOT 40960
// grid = (rows/64, 2): blockIdx.y selects 128-col half.
// MODE 0: implicit-unfold conv from feat, K=576, C=f32 T
// MODE 1: A = relu(T[rowsrc]+tail*w0tail) f32, K=256, C packed u32
// MODE 2: A packed u32, K=256, C packed u32
// MODE 3: MODE2 + fused w4 projection -> g_wp half (Cf + blockIdx.y*NR2*3)
template<int MODE>
__global__ void __launch_bounds__(256, 3)
k_gemm(const float* __restrict__ Af, const uint32_t* __restrict__ Au,
       const uint32_t* __restrict__ W, const float* __restrict__ bias,
       const float* __restrict__ w0tail,
       float* __restrict__ Cf, uint32_t* __restrict__ Cu) {
    constexpr int T = (MODE == 0) ? (D9 / 16) : (HID / 16);
    extern __shared__ __align__(16) char smem[];
    const uint32_t su = smem_u32(smem);
    float* sw0t = (float*)(smem + GB_W0T);

    const int tid = threadIdx.x;
    const int m0 = blockIdx.x * 64;
    const int n0 = blockIdx.y * 128;
    const int arow = tid >> 2, aq = tid & 3;       // 64 rows x 4 col-groups of 4
    const int bcol = tid & 127, bkh = tid >> 7;    // 128 n x 2 k-halves of 8

    if (MODE == 1) {
        for (int i = tid; i < 4 * HID; i += 256) sw0t[i] = w0tail[i];
    }

    int src = 0;
    float t0f = 0.f, t1f = 0.f, t2f = 0.f, t3f = 0.f;
    int fb = 0, fi0 = 0, fj0 = 0;
    if (MODE == 0) {
        int p = m0 + arow;
        fb = p >> 12;
        int pix = p & 4095;
        fi0 = pix >> 6;
        fj0 = pix & 63;
    }
    if (MODE == 1) {
        src = g_rowsrc[m0 + arow];
        const float* tp = &g_tail[(size_t)(m0 + arow) * 4];
        t0f = tp[0]; t1f = tp[1]; t2f = tp[2]; t3f = tp[3];
        __syncthreads();   // sw0t visible
    }

    float    af[4];
    uint32_t au[4];
    uint32_t bw[8];

    auto loadT = [&](int t) {
        int kk = t * 16;
        if (MODE == 0) {
#pragma unroll
            for (int j = 0; j < 4; j++) {
                int c9 = kk + aq * 4 + j;
                int c = c9 / 9;
                int r9 = c9 - c * 9;
                int ki = r9 / 3, kj = r9 - (r9 / 3) * 3;
                int ii = fi0 + ki - 1, jj = fj0 + kj - 1;
                float v = 0.0f;
                if ((unsigned)ii < (unsigned)HQ && (unsigned)jj < (unsigned)WQ)
                    v = Af[(((size_t)fb * DQ + c) * HQ + ii) * WQ + jj];
                af[j] = v;
            }
        } else if (MODE == 1) {
            float4 f0 = *(const float4*)(Af + (size_t)src * HID + kk + aq * 4);
            af[0] = f0.x; af[1] = f0.y; af[2] = f0.z; af[3] = f0.w;
#pragma unroll
            for (int j = 0; j < 4; j++) {
                int c = kk + aq * 4 + j;
                float v = af[j] + t0f * sw0t[c] + t1f * sw0t[HID + c]
                                + t2f * sw0t[2 * HID + c] + t3f * sw0t[3 * HID + c];
                af[j] = fmaxf(v, 0.0f);
            }
        } else {
            uint4 u0 = *(const uint4*)(Au + (size_t)(m0 + arow) * HID + kk + aq * 4);
            au[0] = u0.x; au[1] = u0.y; au[2] = u0.z; au[3] = u0.w;
        }
#pragma unroll
        for (int r = 0; r < 8; r++)
            bw[r] = W[(size_t)(kk + bkh * 8 + r) * HID + n0 + bcol];
    };
    auto storeT = [&](int buf) {
        uint32_t base = (uint32_t)buf * GB_BUF;
        uint32_t hw[2], lw[2];
#pragma unroll
        for (int j = 0; j < 2; j++) {
            ushortt h0, h1, l0, l1;
            if (MODE < 2) {
                float v0 = af[2 * j], v1 = af[2 * j + 1];
                h0 = f2b(v0); l0 = f2b(v0 - b2f(h0));
                h1 = f2b(v1); l1 = f2b(v1 - b2f(h1));
            } else {
                h0 = (ushortt)(au[2 * j] & 0xffff);     l0 = (ushortt)(au[2 * j] >> 16);
                h1 = (ushortt)(au[2 * j + 1] & 0xffff); l1 = (ushortt)(au[2 * j + 1] >> 16);
            }
            hw[j] = (uint32_t)h0 | ((uint32_t)h1 << 16);
            lw[j] = (uint32_t)l0 | ((uint32_t)l1 << 16);
        }
        uint32_t aoff = base + (uint32_t)arow * 48u + (uint32_t)aq * 8u;
        *(uint2*)(smem + aoff)         = make_uint2(hw[0], hw[1]);
        *(uint2*)(smem + aoff + GB_AL) = make_uint2(lw[0], lw[1]);
        uint32_t bh[4], blo[4];
#pragma unroll
        for (int j = 0; j < 4; j++) {
            ushortt h0 = (ushortt)(bw[2 * j] & 0xffff);
            ushortt h1 = (ushortt)(bw[2 * j + 1] & 0xffff);
            ushortt l0 = (ushortt)(bw[2 * j] >> 16);
            ushortt l1 = (ushortt)(bw[2 * j + 1] >> 16);
            bh[j]  = (uint32_t)h0 | ((uint32_t)h1 << 16);
            blo[j] = (uint32_t)l0 | ((uint32_t)l1 << 16);
        }
        uint32_t boff = base + GB_BH + (uint32_t)bcol * 48u + (uint32_t)bkh * 16u;
        *(uint4*)(smem + boff) = make_uint4(bh[0], bh[1], bh[2], bh[3]);
        *(uint4*)(smem + boff + (GB_BL - GB_BH)) = make_uint4(blo[0], blo[1], blo[2], blo[3]);
    };

    const int warp = tid >> 5, lane = tid & 31;
    const int wm = warp & 1, wn = warp >> 1;       // 2 x 4, warp tile 32x32
    const int g = lane >> 2, tg = lane & 3;
    const uint32_t lrow = (uint32_t)(lane & 15);
    const uint32_t lseg = (uint32_t)(lane >> 4) * 16u;
    const uint32_t brow = (uint32_t)((lane & 7) + ((lane >> 4) << 3));
    const uint32_t bkoff = (uint32_t)(((lane >> 3) & 1) << 3) * 2u;   // bytes

    float acc[2][4][4];
#pragma unroll
    for (int mf = 0; mf < 2; mf++)
#pragma unroll
        for (int nf = 0; nf < 4; nf++)
#pragma unroll
            for (int ci = 0; ci < 4; ci++) acc[mf][nf][ci] = 0.0f;

    loadT(0);
    for (int t = 0; t < T; t++) {
        int buf = t & 1;
        storeT(buf);
        __syncthreads();
        if (t + 1 < T) loadT(t + 1);

        uint32_t base = su + (uint32_t)buf * GB_BUF;
        unsigned aH[2][4], aL[2][4];
#pragma unroll
        for (int mf = 0; mf < 2; mf++) {
            uint32_t ra = base + (uint32_t)(wm * 32 + mf * 16) * 48u + lrow * 48u + lseg;
            ldm4(aH[mf][0], aH[mf][1], aH[mf][2], aH[mf][3], ra);
            ldm4(aL[mf][0], aL[mf][1], aL[mf][2], aL[mf][3], ra + GB_AL);
        }
#pragma unroll
        for (int np = 0; np < 2; np++) {
            uint32_t rb = base + GB_BH + (uint32_t)(wn * 32 + np * 16) * 48u +
                          brow * 48u + bkoff;
            unsigned bh0, bh1, bh2, bh3, bl0, bl1, bl2, bl3;
            ldm4(bh0, bh1, bh2, bh3, rb);
            ldm4(bl0, bl1, bl2, bl3, rb + (GB_BL - GB_BH));
            int nf0 = np * 2, nf1 = np * 2 + 1;
#pragma unroll
            for (int mf = 0; mf < 2; mf++) mma_bf16(acc[mf][nf0], aH[mf], bh0, bh1);
#pragma unroll
            for (int mf = 0; mf < 2; mf++) mma_bf16(acc[mf][nf1], aH[mf], bh2, bh3);
#pragma unroll
            for (int mf = 0; mf < 2; mf++) mma_bf16(acc[mf][nf0], aH[mf], bl0, bl1);
#pragma unroll
            for (int mf = 0; mf < 2; mf++) mma_bf16(acc[mf][nf1], aH[mf], bl2, bl3);
#pragma unroll
            for (int mf = 0; mf < 2; mf++) mma_bf16(acc[mf][nf0], aL[mf], bh0, bh1);
#pragma unroll
            for (int mf = 0; mf < 2; mf++) mma_bf16(acc[mf][nf1], aL[mf], bh2, bh3);
        }
    }

    // ---- epilogue ----
    if (MODE == 3) {
        __syncthreads();
        float* sred = (float*)smem;            // [4][64][3] = 3KB
        float* w4s  = (float*)(smem + 3072);   // 768 floats
        for (int i = tid; i < HID * 3; i += 256) w4s[i] = w0tail[i];
        __syncthreads();
        float s[4][3];
#pragma unroll
        for (int i = 0; i < 4; i++) { s[i][0] = 0.f; s[i][1] = 0.f; s[i][2] = 0.f; }
#pragma unroll
        for (int nf = 0; nf < 4; nf++) {
            int col = n0 + wn * 32 + nf * 8 + tg * 2;
            float bv0 = bias[col], bv1 = bias[col + 1];
            float w00 = w4s[col * 3 + 0], w01 = w4s[col * 3 + 1], w02 = w4s[col * 3 + 2];
            float w10 = w4s[col * 3 + 3], w11 = w4s[col * 3 + 4], w12 = w4s[col * 3 + 5];
#pragma unroll
            for (int mf = 0; mf < 2; mf++) {
                float v00 = fmaxf(acc[mf][nf][0] + bv0, 0.0f);
                float v01 = fmaxf(acc[mf][nf][1] + bv1, 0.0f);
                float v10 = fmaxf(acc[mf][nf][2] + bv0, 0.0f);
                float v11 = fmaxf(acc[mf][nf][3] + bv1, 0.0f);
                int i0 = mf * 2, i1 = mf * 2 + 1;
                s[i0][0] += v00 * w00 + v01 * w10;
                s[i0][1] += v00 * w01 + v01 * w11;
                s[i0][2] += v00 * w02 + v01 * w12;
                s[i1][0] += v10 * w00 + v11 * w10;
                s[i1][1] += v10 * w01 + v11 * w11;
                s[i1][2] += v10 * w02 + v11 * w12;
            }
        }
#pragma unroll
        for (int i = 0; i < 4; i++)
#pragma unroll
            for (int c = 0; c < 3; c++) {
                s[i][c] += __shfl_xor_sync(0xffffffffu, s[i][c], 1);
                s[i][c] += __shfl_xor_sync(0xffffffffu, s[i][c], 2);
            }
        if (tg == 0) {
#pragma unroll
            for (int mf = 0; mf < 2; mf++)
#pragma unroll
                for (int hh = 0; hh < 2; hh++) {
                    int row = wm * 32 + mf * 16 + g + hh * 8;
                    int i = mf * 2 + hh;
                    sred[(wn * 64 + row) * 3 + 0] = s[i][0];
                    sred[(wn * 64 + row) * 3 + 1] = s[i][1];
                    sred[(wn * 64 + row) * 3 + 2] = s[i][2];
                }
        }
        __syncthreads();
        float* outp = Cf + (size_t)blockIdx.y * NR2 * 3;
        for (int i = tid; i < 64 * 3; i += 256) {
            int row = i / 3, c = i % 3;
            float sum = sred[(0 * 64 + row) * 3 + c] + sred[(1 * 64 + row) * 3 + c]
                      + sred[(2 * 64 + row) * 3 + c] + sred[(3 * 64 + row) * 3 + c];
            outp[(size_t)(m0 + row) * 3 + c] = g_rwt[m0 + row] * sum;
        }
        return;
    }
#pragma unroll
    for (int nf = 0; nf < 4; nf++) {
        int col = n0 + wn * 32 + nf * 8 + tg * 2;
        float bv0 = bias[col], bv1 = bias[col + 1];
#pragma unroll
        for (int mf = 0; mf < 2; mf++) {
            int row0 = m0 + wm * 32 + mf * 16 + g;
            if (MODE == 0) {
                *(float2*)&Cf[(size_t)row0 * HID + col] =
                    make_float2(acc[mf][nf][0] + bv0, acc[mf][nf][1] + bv1);
                *(float2*)&Cf[(size_t)(row0 + 8) * HID + col] =
                    make_float2(acc[mf][nf][2] + bv0, acc[mf][nf][3] + bv1);
            } else {
                float v00 = fmaxf(acc[mf][nf][0] + bv0, 0.0f);
                float v01 = fmaxf(acc[mf][nf][1] + bv1, 0.0f);
                float v10 = fmaxf(acc[mf][nf][2] + bv0, 0.0f);
                float v11 = fmaxf(acc[mf][nf][3] + bv1, 0.0f);
                *(uint2*)&Cu[(size_t)row0 * HID + col] =
                    make_uint2(packsplit(v00), packsplit(v01));
                *(uint2*)&Cu[(size_t)(row0 + 8) * HID + col] =
                    make_uint2(packsplit(v10), packsplit(v11));
            }
        }
    }
}

// ---------------- combine: sum col halves, then blend branches ----------------
__global__ void k_comb(const float* __restrict__ wp, const float* __restrict__ b4,
                       float* __restrict__ out) {
    int q = blockIdx.x * blockDim.x + threadIdx.x;
    if (q >= BQ * NQ) return;
    int pg = g_qpc[q];
    float b40 = b4[0], b41 = b4[1], b42 = b4[2];
    const float* wp1 = wp + (size_t)NR2 * 3;
    float pa0 = 0.f, pa1 = 0.f, pa2 = 0.f, pl0 = 0.f, pl1 = 0.f, pl2 = 0.f;
#pragma unroll
    for (int k = 0; k < 4; k++) {
        size_t ra = (size_t)(pg * 4 + k) * 3;
        pa0 += wp[ra + 0] + wp1[ra + 0];
        pa1 += wp[ra + 1] + wp1[ra + 1];
        pa2 += wp[ra + 2] + wp1[ra + 2];
        size_t rl = (size_t)(ATTR + q * 4 + k) * 3;
        pl0 += wp[rl + 0] + wp1[rl + 0];
        pl1 += wp[rl + 1] + wp1[rl + 1];
        pl2 += wp[rl + 2] + wp1[rl + 2];
    }
    out[(size_t)q * 3 + 0] = 0.5f * (pa0 + b40) + 0.5f * (pl0 + b40);
    out[(size_t)q * 3 + 1] = 0.5f * (pa1 + b41) + 0.5f * (pl1 + b41);
    out[(size_t)q * 3 + 2] = 0.5f * (pa2 + b42) + 0.5f * (pl2 + b42);
}

// ---------------- launch ----------------
extern "C" void kernel_launch(void* const* d_in, const int* in_sizes, int n_in,
                              void* d_out, int out_size) {
    const float* feat  = (const float*)d_in[0];
    const float* attn  = (const float*)d_in[1];
    const float* coord = (const float*)d_in[2];
    const float* cell  = (const float*)d_in[3];
    const float* w0 = (const float*)d_in[4];
    const float* b0 = (const float*)d_in[5];
    const float* w1 = (const float*)d_in[6];
    const float* b1 = (const float*)d_in[7];
    const float* w2 = (const float*)d_in[8];
    const float* b2 = (const float*)d_in[9];
    const float* w3 = (const float*)d_in[10];
    const float* b3 = (const float*)d_in[11];
    const float* w4 = (const float*)d_in[12];
    const float* b4 = (const float*)d_in[13];
    float* out = (float*)d_out;

    float *Tt, *WP;
    uint32_t *H1, *H2, *W0f, *Wp;
    cudaGetSymbolAddress((void**)&Tt,  g_T);
    cudaGetSymbolAddress((void**)&H1,  g_H1);
    cudaGetSymbolAddress((void**)&H2,  g_H2);
    cudaGetSymbolAddress((void**)&W0f, g_W0f32);
    cudaGetSymbolAddress((void**)&Wp,  g_Wp32);
    cudaGetSymbolAddress((void**)&WP,  g_wp);
    const float* w0tail = w0 + (size_t)D9 * HID;

    static int once = 0;
    static cudaStream_t s2;
    static cudaEvent_t evF, evJ;
    if (!once) {
        cudaFuncSetAttribute(k_gemm<0>, cudaFuncAttributeMaxDynamicSharedMemorySize, GSM_TOT);
        cudaFuncSetAttribute(k_gemm<1>, cudaFuncAttributeMaxDynamicSharedMemorySize, GSM_TOT);
        cudaFuncSetAttribute(k_gemm<2>, cudaFuncAttributeMaxDynamicSharedMemorySize, GSM_TOT);
        cudaFuncSetAttribute(k_gemm<3>, cudaFuncAttributeMaxDynamicSharedMemorySize, GSM_TOT);
        cudaStreamCreateWithFlags(&s2, cudaStreamNonBlocking);
        cudaEventCreateWithFlags(&evF, cudaEventDisableTiming);
        cudaEventCreateWithFlags(&evJ, cudaEventDisableTiming);
        once = 1;
    }

    // fork: top-k / build chain on s2, weight-prep + gemm0 on main stream
    cudaEventRecord(evF, 0);
    cudaStreamWaitEvent(s2, evF, 0);
    k_argmax<<<(BQ * HWQ + 255) / 256, 256, 0, s2>>>(attn);
    k_top4a<<<BQ * NCHUNK, 256, 0, s2>>>(attn);
    k_top4b<<<1, 256, 0, s2>>>();
    k_build<<<(BQ * HWQ + BQ * NQ + 255) / 256, 256, 0, s2>>>(coord, cell);
    cudaEventRecord(evJ, s2);

    int prepn = D9 * HID + 3 * HID * HID;
    k_prepw<<<(prepn + 255) / 256, 256>>>(w0, w1, w2, w3);
    // T = conv3x3(feat, w0_feat) + b0  (implicit unfold)
    k_gemm<0><<<dim3(NPIX / 64, 2), 256, GSM_TOT>>>(feat, nullptr, W0f, b0, nullptr,
                                                    Tt, nullptr);

    cudaStreamWaitEvent(0, evJ, 0);   // join before gemm1 (needs rowsrc/tail/rwt)
    k_gemm<1><<<dim3(NR2 / 64, 2), 256, GSM_TOT>>>(Tt, nullptr, Wp, b1, w0tail,
                                                   nullptr, H1);
    k_gemm<2><<<dim3(NR2 / 64, 2), 256, GSM_TOT>>>(nullptr, H1, Wp + HID * HID, b2,
                                                   nullptr, nullptr, H2);
    k_gemm<3><<<dim3(NR2 / 64, 2), 256, GSM_TOT>>>(nullptr, H2, Wp + 2 * HID * HID, b3,
                                                   w4, WP, nullptr);

    k_comb<<<(BQ * NQ + 255) / 256, 256>>>(WP, b4, out);
}

// round 14
// speedup vs baseline: 1.0683x; 1.0683x over previous
#include <cuda_runtime.h>
#include <cuda_bf16.h>
#include <cstdint>

// ---------------- problem constants ----------------
#define BQ   4
#define DQ   64
#define HQ   64
#define WQ   64
#define HWQ  4096
#define SQ   64
#define NQ   8192
#define KQ   4
#define D9   576
#define HID  256
#define NPIX 16384        // B*HWQ distinct pixel rows
#define ATTR 65536        // attention MLP rows: B*HWQ*4
#define NR2  196608       // ATTR + B*NQ*4 local rows
#define NCHUNK 128

typedef unsigned short ushortt;

// ---------------- device scratch ----------------
__device__ int      g_segm[BQ * HWQ];
__device__ float    g_partv[BQ * NCHUNK * SQ * KQ];
__device__ int      g_parti[BQ * NCHUNK * SQ * KQ];
__device__ float    g_top4v[BQ * SQ * KQ];
__device__ int      g_top4i[BQ * SQ * KQ];
__device__ uint32_t g_W0f32[D9 * HID];                  // packed (hi|lo<<16) bf16
__device__ uint32_t g_Wp32[3 * HID * HID];              // w1..w3 packed [k][n]
__device__ __align__(16) float    g_T[(size_t)NPIX * HID];   // 16.8MB
__device__ uint32_t g_H1[(size_t)NR2 * HID];            // packed hidden activations
__device__ uint32_t g_H2[(size_t)NR2 * HID];
__device__ int      g_rowsrc[NR2];                      // T-row index per MLP row
__device__ float    g_tail[(size_t)NR2 * 4];
__device__ float    g_rwt[NR2];                         // per-row ensemble weight
__device__ int      g_qpc[BQ * NQ];                     // query -> (b*4096+pc1d)
__device__ float    g_wp[(size_t)NR2 * 3];              // per-row weighted prediction

// ---------------- helpers ----------------
__device__ __forceinline__ ushortt f2b(float x) {
    return __bfloat16_as_ushort(__float2bfloat16_rn(x));
}
__device__ __forceinline__ float b2f(ushortt u) {
    return __bfloat162float(__ushort_as_bfloat16(u));
}
__device__ __forceinline__ uint32_t packsplit(float v) {
    ushortt h = f2b(v);
    ushortt l = f2b(v - b2f(h));
    return (uint32_t)h | ((uint32_t)l << 16);
}
__device__ __forceinline__ uint32_t smem_u32(const void* p) {
    uint32_t a;
    asm("{ .reg .u64 t; cvta.to.shared.u64 t, %1; cvt.u32.u64 %0, t; }" : "=r"(a) : "l"(p));
    return a;
}
__device__ __forceinline__ void mma_bf16(float* c, const unsigned* a,
                                         unsigned b0, unsigned b1) {
    asm volatile(
        "mma.sync.aligned.m16n8k16.row.col.f32.bf16.bf16.f32 "
        "{%0,%1,%2,%3},{%4,%5,%6,%7},{%8,%9},{%0,%1,%2,%3};\n"
        : "+f"(c[0]), "+f"(c[1]), "+f"(c[2]), "+f"(c[3])
        : "r"(a[0]), "r"(a[1]), "r"(a[2]), "r"(a[3]), "r"(b0), "r"(b1));
}
__device__ __forceinline__ void ldm4(unsigned& r0, unsigned& r1, unsigned& r2,
                                     unsigned& r3, uint32_t addr) {
    asm volatile("ldmatrix.sync.aligned.m8n8.x4.shared.b16 {%0,%1,%2,%3}, [%4];"
                 : "=r"(r0), "=r"(r1), "=r"(r2), "=r"(r3) : "r"(addr));
}
// top-4 insertion, lax.top_k tie semantics
__device__ __forceinline__ void ins4(float v[4], int id[4], float val, int p) {
    if (!(val > v[3] || (val == v[3] && p < id[3]))) return;
    int pos = 3;
    while (pos > 0 && (val > v[pos - 1] || (val == v[pos - 1] && p < id[pos - 1]))) pos--;
    for (int q = 3; q > pos; q--) { v[q] = v[q - 1]; id[q] = id[q - 1]; }
    v[pos] = val; id[pos] = p;
}

// ---------------- prep ----------------
__global__ void k_prepw(const float* __restrict__ w0, const float* __restrict__ w1,
                        const float* __restrict__ w2, const float* __restrict__ w3) {
    int t = blockIdx.x * blockDim.x + threadIdx.x;
    const int n0 = D9 * HID;
    if (t < n0) {
        g_W0f32[t] = packsplit(w0[t]);
        return;
    }
    int t2 = t - n0;
    if (t2 >= 3 * HID * HID) return;
    int layer = t2 / (HID * HID);
    int i = t2 % (HID * HID);
    const float* w = (layer == 0) ? w1 : (layer == 1) ? w2 : w3;
    g_Wp32[t2] = packsplit(w[i]);
}

// ---------------- argmax ----------------
__global__ void k_argmax(const float* __restrict__ attn) {
    int t = blockIdx.x * blockDim.x + threadIdx.x;
    if (t >= BQ * HWQ) return;
    const float* row = attn + (size_t)t * SQ;
    float best = row[0]; int bi = 0;
    for (int s = 1; s < SQ; s++) {
        float v = row[s];
        if (v > best) { best = v; bi = s; }
    }
    g_segm[t] = bi;
}

// ---------------- top4 stage A ----------------
__global__ void k_top4a(const float* __restrict__ attn) {
    __shared__ float tile[32][SQ + 1];
    __shared__ float sv[4][SQ][4];
    __shared__ int   si[4][SQ][4];
    int b = blockIdx.x >> 7;
    int chunk = blockIdx.x & 127;
    int tid = threadIdx.x;
    int s = tid & 63, sub = tid >> 6;
    int p0 = chunk * 32;
    for (int i = tid; i < 32 * SQ; i += 256) {
        int r = i >> 6, c = i & 63;
        tile[r][c] = attn[((size_t)(b * HWQ) + p0 + r) * SQ + c];
    }
    __syncthreads();
    float v[4]  = {-1e30f, -1e30f, -1e30f, -1e30f};
    int   id[4] = {0x7fffffff, 0x7fffffff, 0x7fffffff, 0x7fffffff};
    for (int rr = 0; rr < 8; rr++) {
        int r = sub * 8 + rr;
        ins4(v, id, tile[r][s], p0 + r);
    }
    for (int q = 0; q < 4; q++) { sv[sub][s][q] = v[q]; si[sub][s][q] = id[q]; }
    __syncthreads();
    if (sub == 0) {
        float fv[4]  = {-1e30f, -1e30f, -1e30f, -1e30f};
        int   fi[4]  = {0x7fffffff, 0x7fffffff, 0x7fffffff, 0x7fffffff};
        for (int ss = 0; ss < 4; ss++)
            for (int q = 0; q < 4; q++)
                ins4(fv, fi, sv[ss][s][q], si[ss][s][q]);
        int base = ((b * NCHUNK + chunk) * SQ + s) * 4;
        for (int q = 0; q < 4; q++) { g_partv[base + q] = fv[q]; g_parti[base + q] = fi[q]; }
    }
}

// ---------------- top4 stage B ----------------
__global__ void k_top4b() {
    int t = threadIdx.x;
    int b = t >> 6, s = t & 63;
    float v[4]  = {-1e30f, -1e30f, -1e30f, -1e30f};
    int   id[4] = {0x7fffffff, 0x7fffffff, 0x7fffffff, 0x7fffffff};
    for (int ch = 0; ch < NCHUNK; ch++) {
        int base = ((b * NCHUNK + ch) * SQ + s) * 4;
        for (int q = 0; q < 4; q++) ins4(v, id, g_partv[base + q], g_parti[base + q]);
    }
    int o = (b * SQ + s) * 4;
    for (int q = 0; q < 4; q++) { g_top4v[o + q] = v[q]; g_top4i[o + q] = id[q]; }
}

// ---------------- build ----------------
__global__ void k_build(const float* __restrict__ coord,
                        const float* __restrict__ cell) {
    int t = blockIdx.x * blockDim.x + threadIdx.x;
    if (t < BQ * HWQ) {
        int b = t >> 12;          // HWQ = 4096
        int pc1d = t & 4095;
        int segm = g_segm[b * HWQ + pc1d];
        const float* tv = &g_top4v[(b * SQ + segm) * 4];
        const int*   ti = &g_top4i[(b * SQ + segm) * 4];
        float sum = tv[0] + tv[1] + tv[2] + tv[3];
        size_t cb = (size_t)b * NQ * 2;   // cell uniform per batch
        float rc0 = cell[cb] * (float)HQ, rc1 = cell[cb + 1] * (float)WQ;
        for (int k = 0; k < 4; k++) {
            int rc = ti[k];
            int rrc = rc - pc1d;
            float rel0 = (float)(rrc >> 6) * (1.0f / (float)HQ);
            float rel1 = (float)(rrc & 63) * (1.0f / (float)WQ);
            int rowr = t * 4 + k;
            g_rowsrc[rowr] = rc;             // batch-0 row of T (faithful)
            g_tail[(size_t)rowr * 4 + 0] = rel0;
            g_tail[(size_t)rowr * 4 + 1] = rel1;
            g_tail[(size_t)rowr * 4 + 2] = rc0;
            g_tail[(size_t)rowr * 4 + 3] = rc1;
            g_rwt[rowr] = tv[k] / sum;
        }
        return;
    }
    int q = t - BQ * HWQ;
    if (q >= BQ * NQ) return;
    int b = q >> 13;
    size_t cb = (size_t)q * 2;
    float c0 = coord[cb], c1 = coord[cb + 1];
    float rc0 = cell[cb] * (float)HQ, rc1 = cell[cb + 1] * (float)WQ;

    float pcf0 = (c0 + 1.0f) / 2.0f * (float)HQ;
    float pcf1 = (c1 + 1.0f) / 2.0f * (float)WQ;
    int pc0 = (int)pcf0; pc0 = max(0, min(HWQ - 1, pc0));
    int pc1 = (int)pcf1; pc1 = max(0, min(HWQ - 1, pc1));
    int pc1d = pc0 * HQ + pc1;
    pc1d = max(0, min(HWQ - 1, pc1d));
    g_qpc[q] = b * HWQ + pc1d;

    const float offv[4][2] = {{-1.f, -1.f}, {-1.f, 1.f}, {1.f, -1.f}, {1.f, 1.f}};
    float area[4];
    for (int j = 0; j < 4; j++) {
        float rx = 1.0f / (float)HQ, ry = 1.0f / (float)WQ;
        float cc0 = c0 + offv[j][0] * rx + 1e-6f;
        float cc1 = c1 + offv[j][1] * ry + 1e-6f;
        cc0 = fminf(fmaxf(cc0, -1.0f + 1e-6f), 1.0f - 1e-6f);
        cc1 = fminf(fmaxf(cc1, -1.0f + 1e-6f), 1.0f - 1e-6f);
        float fy = ((cc0 + 1.0f) * (float)HQ - 1.0f) / 2.0f;
        float fx = ((cc1 + 1.0f) * (float)WQ - 1.0f) / 2.0f;
        int iy = (int)rintf(fy); iy = max(0, min(HQ - 1, iy));
        int ix = (int)rintf(fx); ix = max(0, min(WQ - 1, ix));
        int flat = iy * WQ + ix;
        float qc0 = -1.0f + (2.0f * (float)iy + 1.0f) / (float)HQ;
        float qc1 = -1.0f + (2.0f * (float)ix + 1.0f) / (float)WQ;
        float r0 = (c0 - qc0) * (float)HQ;
        float r1 = (c1 - qc1) * (float)WQ;
        int rowr = ATTR + q * 4 + j;
        g_rowsrc[rowr] = b * HWQ + flat;
        g_tail[(size_t)rowr * 4 + 0] = r0;
        g_tail[(size_t)rowr * 4 + 1] = r1;
        g_tail[(size_t)rowr * 4 + 2] = rc0;
        g_tail[(size_t)rowr * 4 + 3] = rc1;
        area[j] = fabsf(r0 * r1) + 1e-9f;
    }
    float tot = area[0] + area[1] + area[2] + area[3];
    for (int j = 0; j < 4; j++) g_rwt[ATTR + q * 4 + j] = area[3 - j] / tot;
}

// ---------------- GEMM: BM=64 BN=256 BK=16, 2 CTAs/SM, ldmatrix ----------------
// per buffer (bytes): AH 0 (64x48=3072), AL 3072, BH 6144 (256x48=12288), BL 18432
//   -> buffer = 30720; two buffers 61440; sw0t @61440 (4KB); total 65536
#define GB_BUF 30720u
#define GB_AL  3072u
#define GB_BH  6144u
#define GB_BL  18432u
#define GB_W0T 61440u
#define GSM_TOT 65536
// grid = rows/64 (full 256-col width per CTA)
// MODE 0: implicit-unfold conv from feat, K=576, C=f32 T
// MODE 1: A = relu(T[rowsrc]+tail*w0tail) f32, K=256, C packed u32
// MODE 2: A packed u32, K=256, C packed u32
// MODE 3: MODE2 + fused w4 projection -> g_wp
template<int MODE>
__global__ void __launch_bounds__(256, 2)
k_gemm(const float* __restrict__ Af, const uint32_t* __restrict__ Au,
       const uint32_t* __restrict__ W, const float* __restrict__ bias,
       const float* __restrict__ w0tail,
       float* __restrict__ Cf, uint32_t* __restrict__ Cu) {
    constexpr int T = (MODE == 0) ? (D9 / 16) : (HID / 16);
    extern __shared__ __align__(16) char smem[];
    const uint32_t su = smem_u32(smem);
    float* sw0t = (float*)(smem + GB_W0T);

    const int tid = threadIdx.x;
    const int m0 = blockIdx.x * 64;
    const int arow = tid >> 2, aq = tid & 3;   // 64 rows x 4 col-groups of 4

    if (MODE == 1) {
        for (int i = tid; i < 4 * HID; i += 256) sw0t[i] = w0tail[i];
    }

    int src = 0;
    float t0f = 0.f, t1f = 0.f, t2f = 0.f, t3f = 0.f;
    int fb = 0, fi0 = 0, fj0 = 0;
    if (MODE == 0) {
        int p = m0 + arow;
        fb = p >> 12;
        int pix = p & 4095;
        fi0 = pix >> 6;
        fj0 = pix & 63;
    }
    if (MODE == 1) {
        src = g_rowsrc[m0 + arow];
        const float* tp = &g_tail[(size_t)(m0 + arow) * 4];
        t0f = tp[0]; t1f = tp[1]; t2f = tp[2]; t3f = tp[3];
        __syncthreads();   // sw0t visible
    }

    float    af[4];
    uint32_t au[4];
    uint32_t bw[16];

    auto loadT = [&](int t) {
        int kk = t * 16;
        if (MODE == 0) {
#pragma unroll
            for (int j = 0; j < 4; j++) {
                int c9 = kk + aq * 4 + j;
                int c = c9 / 9;
                int r9 = c9 - c * 9;
                int ki = r9 / 3, kj = r9 - (r9 / 3) * 3;
                int ii = fi0 + ki - 1, jj = fj0 + kj - 1;
                float v = 0.0f;
                if ((unsigned)ii < (unsigned)HQ && (unsigned)jj < (unsigned)WQ)
                    v = Af[(((size_t)fb * DQ + c) * HQ + ii) * WQ + jj];
                af[j] = v;
            }
        } else if (MODE == 1) {
            float4 f0 = *(const float4*)(Af + (size_t)src * HID + kk + aq * 4);
            af[0] = f0.x; af[1] = f0.y; af[2] = f0.z; af[3] = f0.w;
#pragma unroll
            for (int j = 0; j < 4; j++) {
                int c = kk + aq * 4 + j;
                float v = af[j] + t0f * sw0t[c] + t1f * sw0t[HID + c]
                                + t2f * sw0t[2 * HID + c] + t3f * sw0t[3 * HID + c];
                af[j] = fmaxf(v, 0.0f);
            }
        } else {
            uint4 u0 = *(const uint4*)(Au + (size_t)(m0 + arow) * HID + kk + aq * 4);
            au[0] = u0.x; au[1] = u0.y; au[2] = u0.z; au[3] = u0.w;
        }
#pragma unroll
        for (int r = 0; r < 16; r++) bw[r] = W[(size_t)(kk + r) * HID + tid];
    };
    auto storeT = [&](int buf) {
        uint32_t base = (uint32_t)buf * GB_BUF;
        uint32_t hw[2], lw[2];
#pragma unroll
        for (int j = 0; j < 2; j++) {
            ushortt h0, h1, l0, l1;
            if (MODE < 2) {
                float v0 = af[2 * j], v1 = af[2 * j + 1];
                h0 = f2b(v0); l0 = f2b(v0 - b2f(h0));
                h1 = f2b(v1); l1 = f2b(v1 - b2f(h1));
            } else {
                h0 = (ushortt)(au[2 * j] & 0xffff);     l0 = (ushortt)(au[2 * j] >> 16);
                h1 = (ushortt)(au[2 * j + 1] & 0xffff); l1 = (ushortt)(au[2 * j + 1] >> 16);
            }
            hw[j] = (uint32_t)h0 | ((uint32_t)h1 << 16);
            lw[j] = (uint32_t)l0 | ((uint32_t)l1 << 16);
        }
        uint32_t aoff = base + (uint32_t)arow * 48u + (uint32_t)aq * 8u;
        *(uint2*)(smem + aoff)         = make_uint2(hw[0], hw[1]);
        *(uint2*)(smem + aoff + GB_AL) = make_uint2(lw[0], lw[1]);
        uint32_t bh[8], blo[8];
#pragma unroll
        for (int j = 0; j < 8; j++) {
            ushortt h0 = (ushortt)(bw[2 * j] & 0xffff);
            ushortt h1 = (ushortt)(bw[2 * j + 1] & 0xffff);
            ushortt l0 = (ushortt)(bw[2 * j] >> 16);
            ushortt l1 = (ushortt)(bw[2 * j + 1] >> 16);
            bh[j]  = (uint32_t)h0 | ((uint32_t)h1 << 16);
            blo[j] = (uint32_t)l0 | ((uint32_t)l1 << 16);
        }
        uint32_t boff = base + GB_BH + (uint32_t)tid * 48u;
        *(uint4*)(smem + boff)      = make_uint4(bh[0], bh[1], bh[2], bh[3]);
        *(uint4*)(smem + boff + 16) = make_uint4(bh[4], bh[5], bh[6], bh[7]);
        uint32_t loff = base + GB_BL + (uint32_t)tid * 48u;
        *(uint4*)(smem + loff)      = make_uint4(blo[0], blo[1], blo[2], blo[3]);
        *(uint4*)(smem + loff + 16) = make_uint4(blo[4], blo[5], blo[6], blo[7]);
    };

    const int warp = tid >> 5, lane = tid & 31;
    const int wm = warp & 1, wn = warp >> 1;       // 2 x 4, warp tile 32x64
    const int g = lane >> 2, tg = lane & 3;
    const uint32_t lrow = (uint32_t)(lane & 15);
    const uint32_t lseg = (uint32_t)(lane >> 4) * 16u;
    const uint32_t brow = (uint32_t)((lane & 7) + ((lane >> 4) << 3));
    const uint32_t bkoff = (uint32_t)(((lane >> 3) & 1) << 3) * 2u;   // bytes

    float acc[2][8][4];
#pragma unroll
    for (int mf = 0; mf < 2; mf++)
#pragma unroll
        for (int nf = 0; nf < 8; nf++)
#pragma unroll
            for (int ci = 0; ci < 4; ci++) acc[mf][nf][ci] = 0.0f;

    loadT(0);
    for (int t = 0; t < T; t++) {
        int buf = t & 1;
        storeT(buf);
        __syncthreads();
        if (t + 1 < T) loadT(t + 1);

        uint32_t base = su + (uint32_t)buf * GB_BUF;
        unsigned aH[2][4], aL[2][4];
#pragma unroll
        for (int mf = 0; mf < 2; mf++) {
            uint32_t ra = base + (uint32_t)(wm * 32 + mf * 16) * 48u + lrow * 48u + lseg;
            ldm4(aH[mf][0], aH[mf][1], aH[mf][2], aH[mf][3], ra);
            ldm4(aL[mf][0], aL[mf][1], aL[mf][2], aL[mf][3], ra + GB_AL);
        }
#pragma unroll
        for (int np = 0; np < 4; np++) {
            uint32_t rb = base + GB_BH + (uint32_t)(wn * 64 + np * 16) * 48u +
                          brow * 48u + bkoff;
            unsigned bh0, bh1, bh2, bh3, bl0, bl1, bl2, bl3;
            ldm4(bh0, bh1, bh2, bh3, rb);
            ldm4(bl0, bl1, bl2, bl3, rb + (GB_BL - GB_BH));
            int nf0 = np * 2, nf1 = np * 2 + 1;
#pragma unroll
            for (int mf = 0; mf < 2; mf++) mma_bf16(acc[mf][nf0], aH[mf], bh0, bh1);
#pragma unroll
            for (int mf = 0; mf < 2; mf++) mma_bf16(acc[mf][nf1], aH[mf], bh2, bh3);
#pragma unroll
            for (int mf = 0; mf < 2; mf++) mma_bf16(acc[mf][nf0], aH[mf], bl0, bl1);
#pragma unroll
            for (int mf = 0; mf < 2; mf++) mma_bf16(acc[mf][nf1], aH[mf], bl2, bl3);
#pragma unroll
            for (int mf = 0; mf < 2; mf++) mma_bf16(acc[mf][nf0], aL[mf], bh0, bh1);
#pragma unroll
            for (int mf = 0; mf < 2; mf++) mma_bf16(acc[mf][nf1], aL[mf], bh2, bh3);
        }
    }

    // ---- epilogue ----
    if (MODE == 3) {
        __syncthreads();
        float* sred = (float*)smem;            // [4][64][3] = 3KB
        float* w4s  = (float*)(smem + 3072);   // 768 floats
        for (int i = tid; i < HID * 3; i += 256) w4s[i] = w0tail[i];
        __syncthreads();
        float s[4][3];
#pragma unroll
        for (int i = 0; i < 4; i++) { s[i][0] = 0.f; s[i][1] = 0.f; s[i][2] = 0.f; }
#pragma unroll
        for (int nf = 0; nf < 8; nf++) {
            int col = wn * 64 + nf * 8 + tg * 2;
            float bv0 = bias[col], bv1 = bias[col + 1];
            float w00 = w4s[col * 3 + 0], w01 = w4s[col * 3 + 1], w02 = w4s[col * 3 + 2];
            float w10 = w4s[col * 3 + 3], w11 = w4s[col * 3 + 4], w12 = w4s[col * 3 + 5];
#pragma unroll
            for (int mf = 0; mf < 2; mf++) {
                float v00 = fmaxf(acc[mf][nf][0] + bv0, 0.0f);
                float v01 = fmaxf(acc[mf][nf][1] + bv1, 0.0f);
                float v10 = fmaxf(acc[mf][nf][2] + bv0, 0.0f);
                float v11 = fmaxf(acc[mf][nf][3] + bv1, 0.0f);
                int i0 = mf * 2, i1 = mf * 2 + 1;
                s[i0][0] += v00 * w00 + v01 * w10;
                s[i0][1] += v00 * w01 + v01 * w11;
                s[i0][2] += v00 * w02 + v01 * w12;
                s[i1][0] += v10 * w00 + v11 * w10;
                s[i1][1] += v10 * w01 + v11 * w11;
                s[i1][2] += v10 * w02 + v11 * w12;
            }
        }
#pragma unroll
        for (int i = 0; i < 4; i++)
#pragma unroll
            for (int c = 0; c < 3; c++) {
                s[i][c] += __shfl_xor_sync(0xffffffffu, s[i][c], 1);
                s[i][c] += __shfl_xor_sync(0xffffffffu, s[i][c], 2);
            }
        if (tg == 0) {
#pragma unroll
            for (int mf = 0; mf < 2; mf++)
#pragma unroll
                for (int hh = 0; hh < 2; hh++) {
                    int row = wm * 32 + mf * 16 + g + hh * 8;
                    int i = mf * 2 + hh;
                    sred[(wn * 64 + row) * 3 + 0] = s[i][0];
                    sred[(wn * 64 + row) * 3 + 1] = s[i][1];
                    sred[(wn * 64 + row) * 3 + 2] = s[i][2];
                }
        }
        __syncthreads();
        for (int i = tid; i < 64 * 3; i += 256) {
            int row = i / 3, c = i % 3;
            float sum = sred[(0 * 64 + row) * 3 + c] + sred[(1 * 64 + row) * 3 + c]
                      + sred[(2 * 64 + row) * 3 + c] + sred[(3 * 64 + row) * 3 + c];
            Cf[(size_t)(m0 + row) * 3 + c] = g_rwt[m0 + row] * sum;
        }
        return;
    }
#pragma unroll
    for (int nf = 0; nf < 8; nf++) {
        int col = wn * 64 + nf * 8 + tg * 2;
        float bv0 = bias[col], bv1 = bias[col + 1];
#pragma unroll
        for (int mf = 0; mf < 2; mf++) {
            int row0 = m0 + wm * 32 + mf * 16 + g;
            if (MODE == 0) {
                *(float2*)&Cf[(size_t)row0 * HID + col] =
                    make_float2(acc[mf][nf][0] + bv0, acc[mf][nf][1] + bv1);
                *(float2*)&Cf[(size_t)(row0 + 8) * HID + col] =
                    make_float2(acc[mf][nf][2] + bv0, acc[mf][nf][3] + bv1);
            } else {
                float v00 = fmaxf(acc[mf][nf][0] + bv0, 0.0f);
                float v01 = fmaxf(acc[mf][nf][1] + bv1, 0.0f);
                float v10 = fmaxf(acc[mf][nf][2] + bv0, 0.0f);
                float v11 = fmaxf(acc[mf][nf][3] + bv1, 0.0f);
                *(uint2*)&Cu[(size_t)row0 * HID + col] =
                    make_uint2(packsplit(v00), packsplit(v01));
                *(uint2*)&Cu[(size_t)(row0 + 8) * HID + col] =
                    make_uint2(packsplit(v10), packsplit(v11));
            }
        }
    }
}

// ---------------- combine: out = 0.5*(attn group) + 0.5*(local group) --------
__global__ void k_comb(const float* __restrict__ wp, const float* __restrict__ b4,
                       float* __restrict__ out) {
    int q = blockIdx.x * blockDim.x + threadIdx.x;
    if (q >= BQ * NQ) return;
    int pg = g_qpc[q];
    float b40 = b4[0], b41 = b4[1], b42 = b4[2];
    float pa0 = 0.f, pa1 = 0.f, pa2 = 0.f, pl0 = 0.f, pl1 = 0.f, pl2 = 0.f;
#pragma unroll
    for (int k = 0; k < 4; k++) {
        size_t ra = (size_t)(pg * 4 + k) * 3;
        pa0 += wp[ra + 0]; pa1 += wp[ra + 1]; pa2 += wp[ra + 2];
        size_t rl = (size_t)(ATTR + q * 4 + k) * 3;
        pl0 += wp[rl + 0]; pl1 += wp[rl + 1]; pl2 += wp[rl + 2];
    }
    out[(size_t)q * 3 + 0] = 0.5f * (pa0 + b40) + 0.5f * (pl0 + b40);
    out[(size_t)q * 3 + 1] = 0.5f * (pa1 + b41) + 0.5f * (pl1 + b41);
    out[(size_t)q * 3 + 2] = 0.5f * (pa2 + b42) + 0.5f * (pl2 + b42);
}

// ---------------- launch ----------------
extern "C" void kernel_launch(void* const* d_in, const int* in_sizes, int n_in,
                              void* d_out, int out_size) {
    const float* feat  = (const float*)d_in[0];
    const float* attn  = (const float*)d_in[1];
    const float* coord = (const float*)d_in[2];
    const float* cell  = (const float*)d_in[3];
    const float* w0 = (const float*)d_in[4];
    const float* b0 = (const float*)d_in[5];
    const float* w1 = (const float*)d_in[6];
    const float* b1 = (const float*)d_in[7];
    const float* w2 = (const float*)d_in[8];
    const float* b2 = (const float*)d_in[9];
    const float* w3 = (const float*)d_in[10];
    const float* b3 = (const float*)d_in[11];
    const float* w4 = (const float*)d_in[12];
    const float* b4 = (const float*)d_in[13];
    float* out = (float*)d_out;

    float *Tt, *WP;
    uint32_t *H1, *H2, *W0f, *Wp;
    cudaGetSymbolAddress((void**)&Tt,  g_T);
    cudaGetSymbolAddress((void**)&H1,  g_H1);
    cudaGetSymbolAddress((void**)&H2,  g_H2);
    cudaGetSymbolAddress((void**)&W0f, g_W0f32);
    cudaGetSymbolAddress((void**)&Wp,  g_Wp32);
    cudaGetSymbolAddress((void**)&WP,  g_wp);
    const float* w0tail = w0 + (size_t)D9 * HID;

    static int once = 0;
    static cudaStream_t s2;
    static cudaEvent_t evF, evJ;
    if (!once) {
        cudaFuncSetAttribute(k_gemm<0>, cudaFuncAttributeMaxDynamicSharedMemorySize, GSM_TOT);
        cudaFuncSetAttribute(k_gemm<1>, cudaFuncAttributeMaxDynamicSharedMemorySize, GSM_TOT);
        cudaFuncSetAttribute(k_gemm<2>, cudaFuncAttributeMaxDynamicSharedMemorySize, GSM_TOT);
        cudaFuncSetAttribute(k_gemm<3>, cudaFuncAttributeMaxDynamicSharedMemorySize, GSM_TOT);
        cudaStreamCreateWithFlags(&s2, cudaStreamNonBlocking);
        cudaEventCreateWithFlags(&evF, cudaEventDisableTiming);
        cudaEventCreateWithFlags(&evJ, cudaEventDisableTiming);
        once = 1;
    }

    // fork: top-k / build chain on s2, weight-prep + gemm0 on main stream
    cudaEventRecord(evF, 0);
    cudaStreamWaitEvent(s2, evF, 0);
    k_argmax<<<(BQ * HWQ + 255) / 256, 256, 0, s2>>>(attn);
    k_top4a<<<BQ * NCHUNK, 256, 0, s2>>>(attn);
    k_top4b<<<1, 256, 0, s2>>>();
    k_build<<<(BQ * HWQ + BQ * NQ + 255) / 256, 256, 0, s2>>>(coord, cell);
    cudaEventRecord(evJ, s2);

    int prepn = D9 * HID + 3 * HID * HID;
    k_prepw<<<(prepn + 255) / 256, 256>>>(w0, w1, w2, w3);
    // T = conv3x3(feat, w0_feat) + b0  (implicit unfold)
    k_gemm<0><<<NPIX / 64, 256, GSM_TOT>>>(feat, nullptr, W0f, b0, nullptr, Tt, nullptr);

    cudaStreamWaitEvent(0, evJ, 0);   // join before gemm1 (needs rowsrc/tail/rwt)
    k_gemm<1><<<NR2 / 64, 256, GSM_TOT>>>(Tt, nullptr, Wp, b1, w0tail, nullptr, H1);
    k_gemm<2><<<NR2 / 64, 256, GSM_TOT>>>(nullptr, H1, Wp + HID * HID, b2, nullptr,
                                          nullptr, H2);
    k_gemm<3><<<NR2 / 64, 256, GSM_TOT>>>(nullptr, H2, Wp + 2 * HID * HID, b3, w4,
                                          WP, nullptr);

    k_comb<<<(BQ * NQ + 255) / 256, 256>>>(WP, b4, out);
}

// round 15
// speedup vs baseline: 1.1817x; 1.1061x over previous
#include <cuda_runtime.h>
#include <cuda_bf16.h>
#include <cstdint>

// ---------------- problem constants ----------------
#define BQ   4
#define DQ   64
#define HQ   64
#define WQ   64
#define HWQ  4096
#define SQ   64
#define NQ   8192
#define KQ   4
#define D9   576
#define HID  256
#define NPIX 16384        // B*HWQ distinct pixel rows
#define ATTR 65536        // attention MLP rows: B*HWQ*4
#define NR2  196608       // ATTR + B*NQ*4 local rows
#define NCHUNK 128

typedef unsigned short ushortt;

// ---------------- device scratch ----------------
__device__ int      g_segm[BQ * HWQ];
__device__ float    g_partv[BQ * NCHUNK * SQ * KQ];
__device__ int      g_parti[BQ * NCHUNK * SQ * KQ];
__device__ float    g_top4v[BQ * SQ * KQ];
__device__ int      g_top4i[BQ * SQ * KQ];
__device__ uint32_t g_W0f32[D9 * HID];                  // packed (hi|lo<<16) bf16
__device__ uint32_t g_Wp32[3 * HID * HID];              // w1..w3 packed [k][n]
__device__ __align__(16) float    g_T[(size_t)NPIX * HID];   // 16.8MB
__device__ int      g_rowsrc[NR2];                      // T-row index per MLP row
__device__ float    g_tail[(size_t)NR2 * 4];
__device__ float    g_rwt[NR2];                         // per-row ensemble weight
__device__ int      g_qpc[BQ * NQ];                     // query -> (b*4096+pc1d)
__device__ float    g_wp[(size_t)NR2 * 3];              // per-row weighted prediction

// ---------------- helpers ----------------
__device__ __forceinline__ ushortt f2b(float x) {
    return __bfloat16_as_ushort(__float2bfloat16_rn(x));
}
__device__ __forceinline__ float b2f(ushortt u) {
    return __bfloat162float(__ushort_as_bfloat16(u));
}
__device__ __forceinline__ uint32_t packsplit(float v) {
    ushortt h = f2b(v);
    ushortt l = f2b(v - b2f(h));
    return (uint32_t)h | ((uint32_t)l << 16);
}
__device__ __forceinline__ uint32_t smem_u32(const void* p) {
    uint32_t a;
    asm("{ .reg .u64 t; cvta.to.shared.u64 t, %1; cvt.u32.u64 %0, t; }" : "=r"(a) : "l"(p));
    return a;
}
__device__ __forceinline__ void mma_bf16(float* c, const unsigned* a,
                                         unsigned b0, unsigned b1) {
    asm volatile(
        "mma.sync.aligned.m16n8k16.row.col.f32.bf16.bf16.f32 "
        "{%0,%1,%2,%3},{%4,%5,%6,%7},{%8,%9},{%0,%1,%2,%3};\n"
        : "+f"(c[0]), "+f"(c[1]), "+f"(c[2]), "+f"(c[3])
        : "r"(a[0]), "r"(a[1]), "r"(a[2]), "r"(a[3]), "r"(b0), "r"(b1));
}
__device__ __forceinline__ void ldm4(unsigned& r0, unsigned& r1, unsigned& r2,
                                     unsigned& r3, uint32_t addr) {
    asm volatile("ldmatrix.sync.aligned.m8n8.x4.shared.b16 {%0,%1,%2,%3}, [%4];"
                 : "=r"(r0), "=r"(r1), "=r"(r2), "=r"(r3) : "r"(addr));
}
// top-4 insertion, lax.top_k tie semantics
__device__ __forceinline__ void ins4(float v[4], int id[4], float val, int p) {
    if (!(val > v[3] || (val == v[3] && p < id[3]))) return;
    int pos = 3;
    while (pos > 0 && (val > v[pos - 1] || (val == v[pos - 1] && p < id[pos - 1]))) pos--;
    for (int q = 3; q > pos; q--) { v[q] = v[q - 1]; id[q] = id[q - 1]; }
    v[pos] = val; id[pos] = p;
}

// ---------------- prep ----------------
__global__ void k_prepw(const float* __restrict__ w0, const float* __restrict__ w1,
                        const float* __restrict__ w2, const float* __restrict__ w3) {
    int t = blockIdx.x * blockDim.x + threadIdx.x;
    const int n0 = D9 * HID;
    if (t < n0) {
        g_W0f32[t] = packsplit(w0[t]);
        return;
    }
    int t2 = t - n0;
    if (t2 >= 3 * HID * HID) return;
    int layer = t2 / (HID * HID);
    int i = t2 % (HID * HID);
    const float* w = (layer == 0) ? w1 : (layer == 1) ? w2 : w3;
    g_Wp32[t2] = packsplit(w[i]);
}

// ---------------- argmax ----------------
__global__ void k_argmax(const float* __restrict__ attn) {
    int t = blockIdx.x * blockDim.x + threadIdx.x;
    if (t >= BQ * HWQ) return;
    const float* row = attn + (size_t)t * SQ;
    float best = row[0]; int bi = 0;
    for (int s = 1; s < SQ; s++) {
        float v = row[s];
        if (v > best) { best = v; bi = s; }
    }
    g_segm[t] = bi;
}

// ---------------- top4 stage A ----------------
__global__ void k_top4a(const float* __restrict__ attn) {
    __shared__ float tile[32][SQ + 1];
    __shared__ float sv[4][SQ][4];
    __shared__ int   si[4][SQ][4];
    int b = blockIdx.x >> 7;
    int chunk = blockIdx.x & 127;
    int tid = threadIdx.x;
    int s = tid & 63, sub = tid >> 6;
    int p0 = chunk * 32;
    for (int i = tid; i < 32 * SQ; i += 256) {
        int r = i >> 6, c = i & 63;
        tile[r][c] = attn[((size_t)(b * HWQ) + p0 + r) * SQ + c];
    }
    __syncthreads();
    float v[4]  = {-1e30f, -1e30f, -1e30f, -1e30f};
    int   id[4] = {0x7fffffff, 0x7fffffff, 0x7fffffff, 0x7fffffff};
    for (int rr = 0; rr < 8; rr++) {
        int r = sub * 8 + rr;
        ins4(v, id, tile[r][s], p0 + r);
    }
    for (int q = 0; q < 4; q++) { sv[sub][s][q] = v[q]; si[sub][s][q] = id[q]; }
    __syncthreads();
    if (sub == 0) {
        float fv[4]  = {-1e30f, -1e30f, -1e30f, -1e30f};
        int   fi[4]  = {0x7fffffff, 0x7fffffff, 0x7fffffff, 0x7fffffff};
        for (int ss = 0; ss < 4; ss++)
            for (int q = 0; q < 4; q++)
                ins4(fv, fi, sv[ss][s][q], si[ss][s][q]);
        int base = ((b * NCHUNK + chunk) * SQ + s) * 4;
        for (int q = 0; q < 4; q++) { g_partv[base + q] = fv[q]; g_parti[base + q] = fi[q]; }
    }
}

// ---------------- top4 stage B ----------------
__global__ void k_top4b() {
    int t = threadIdx.x;
    int b = t >> 6, s = t & 63;
    float v[4]  = {-1e30f, -1e30f, -1e30f, -1e30f};
    int   id[4] = {0x7fffffff, 0x7fffffff, 0x7fffffff, 0x7fffffff};
    for (int ch = 0; ch < NCHUNK; ch++) {
        int base = ((b * NCHUNK + ch) * SQ + s) * 4;
        for (int q = 0; q < 4; q++) ins4(v, id, g_partv[base + q], g_parti[base + q]);
    }
    int o = (b * SQ + s) * 4;
    for (int q = 0; q < 4; q++) { g_top4v[o + q] = v[q]; g_top4i[o + q] = id[q]; }
}

// ---------------- build ----------------
__global__ void k_build(const float* __restrict__ coord,
                        const float* __restrict__ cell) {
    int t = blockIdx.x * blockDim.x + threadIdx.x;
    if (t < BQ * HWQ) {
        int b = t >> 12;          // HWQ = 4096
        int pc1d = t & 4095;
        int segm = g_segm[b * HWQ + pc1d];
        const float* tv = &g_top4v[(b * SQ + segm) * 4];
        const int*   ti = &g_top4i[(b * SQ + segm) * 4];
        float sum = tv[0] + tv[1] + tv[2] + tv[3];
        size_t cb = (size_t)b * NQ * 2;   // cell uniform per batch
        float rc0 = cell[cb] * (float)HQ, rc1 = cell[cb + 1] * (float)WQ;
        for (int k = 0; k < 4; k++) {
            int rc = ti[k];
            int rrc = rc - pc1d;
            float rel0 = (float)(rrc >> 6) * (1.0f / (float)HQ);
            float rel1 = (float)(rrc & 63) * (1.0f / (float)WQ);
            int rowr = t * 4 + k;
            g_rowsrc[rowr] = rc;             // batch-0 row of T (faithful)
            g_tail[(size_t)rowr * 4 + 0] = rel0;
            g_tail[(size_t)rowr * 4 + 1] = rel1;
            g_tail[(size_t)rowr * 4 + 2] = rc0;
            g_tail[(size_t)rowr * 4 + 3] = rc1;
            g_rwt[rowr] = tv[k] / sum;
        }
        return;
    }
    int q = t - BQ * HWQ;
    if (q >= BQ * NQ) return;
    int b = q >> 13;
    size_t cb = (size_t)q * 2;
    float c0 = coord[cb], c1 = coord[cb + 1];
    float rc0 = cell[cb] * (float)HQ, rc1 = cell[cb + 1] * (float)WQ;

    float pcf0 = (c0 + 1.0f) / 2.0f * (float)HQ;
    float pcf1 = (c1 + 1.0f) / 2.0f * (float)WQ;
    int pc0 = (int)pcf0; pc0 = max(0, min(HWQ - 1, pc0));
    int pc1 = (int)pcf1; pc1 = max(0, min(HWQ - 1, pc1));
    int pc1d = pc0 * HQ + pc1;
    pc1d = max(0, min(HWQ - 1, pc1d));
    g_qpc[q] = b * HWQ + pc1d;

    const float offv[4][2] = {{-1.f, -1.f}, {-1.f, 1.f}, {1.f, -1.f}, {1.f, 1.f}};
    float area[4];
    for (int j = 0; j < 4; j++) {
        float rx = 1.0f / (float)HQ, ry = 1.0f / (float)WQ;
        float cc0 = c0 + offv[j][0] * rx + 1e-6f;
        float cc1 = c1 + offv[j][1] * ry + 1e-6f;
        cc0 = fminf(fmaxf(cc0, -1.0f + 1e-6f), 1.0f - 1e-6f);
        cc1 = fminf(fmaxf(cc1, -1.0f + 1e-6f), 1.0f - 1e-6f);
        float fy = ((cc0 + 1.0f) * (float)HQ - 1.0f) / 2.0f;
        float fx = ((cc1 + 1.0f) * (float)WQ - 1.0f) / 2.0f;
        int iy = (int)rintf(fy); iy = max(0, min(HQ - 1, iy));
        int ix = (int)rintf(fx); ix = max(0, min(WQ - 1, ix));
        int flat = iy * WQ + ix;
        float qc0 = -1.0f + (2.0f * (float)iy + 1.0f) / (float)HQ;
        float qc1 = -1.0f + (2.0f * (float)ix + 1.0f) / (float)WQ;
        float r0 = (c0 - qc0) * (float)HQ;
        float r1 = (c1 - qc1) * (float)WQ;
        int rowr = ATTR + q * 4 + j;
        g_rowsrc[rowr] = b * HWQ + flat;
        g_tail[(size_t)rowr * 4 + 0] = r0;
        g_tail[(size_t)rowr * 4 + 1] = r1;
        g_tail[(size_t)rowr * 4 + 2] = rc0;
        g_tail[(size_t)rowr * 4 + 3] = rc1;
        area[j] = fabsf(r0 * r1) + 1e-9f;
    }
    float tot = area[0] + area[1] + area[2] + area[3];
    for (int j = 0; j < 4; j++) g_rwt[ATTR + q * 4 + j] = area[3 - j] / tot;
}

// ---------------- T-gemm: implicit-unfold conv, BM=64 BN=256 (from R14) --------
#define GB_BUF 30720u
#define GB_AL  3072u
#define GB_BH  6144u
#define GB_BL  18432u
#define GSM_TOT 61440
__global__ void __launch_bounds__(256, 2)
k_tgemm(const float* __restrict__ Af, const uint32_t* __restrict__ W,
        const float* __restrict__ bias, float* __restrict__ Cf) {
    constexpr int T = D9 / 16;
    extern __shared__ __align__(16) char smem[];
    const uint32_t su = smem_u32(smem);
    const int tid = threadIdx.x;
    const int m0 = blockIdx.x * 64;
    const int arow = tid >> 2, aq = tid & 3;
    int p = m0 + arow;
    int fb = p >> 12;
    int pix = p & 4095;
    int fi0 = pix >> 6, fj0 = pix & 63;

    float    af[4];
    uint32_t bw[16];
    auto loadT = [&](int t) {
        int kk = t * 16;
#pragma unroll
        for (int j = 0; j < 4; j++) {
            int c9 = kk + aq * 4 + j;
            int c = c9 / 9;
            int r9 = c9 - c * 9;
            int ki = r9 / 3, kj = r9 - (r9 / 3) * 3;
            int ii = fi0 + ki - 1, jj = fj0 + kj - 1;
            float v = 0.0f;
            if ((unsigned)ii < (unsigned)HQ && (unsigned)jj < (unsigned)WQ)
                v = Af[(((size_t)fb * DQ + c) * HQ + ii) * WQ + jj];
            af[j] = v;
        }
#pragma unroll
        for (int r = 0; r < 16; r++) bw[r] = W[(size_t)(kk + r) * HID + tid];
    };
    auto storeT = [&](int buf) {
        uint32_t base = (uint32_t)buf * GB_BUF;
        uint32_t hw[2], lw[2];
#pragma unroll
        for (int j = 0; j < 2; j++) {
            float v0 = af[2 * j], v1 = af[2 * j + 1];
            ushortt h0 = f2b(v0), h1 = f2b(v1);
            ushortt l0 = f2b(v0 - b2f(h0)), l1 = f2b(v1 - b2f(h1));
            hw[j] = (uint32_t)h0 | ((uint32_t)h1 << 16);
            lw[j] = (uint32_t)l0 | ((uint32_t)l1 << 16);
        }
        uint32_t aoff = base + (uint32_t)arow * 48u + (uint32_t)aq * 8u;
        *(uint2*)(smem + aoff)         = make_uint2(hw[0], hw[1]);
        *(uint2*)(smem + aoff + GB_AL) = make_uint2(lw[0], lw[1]);
        uint32_t bh[8], blo[8];
#pragma unroll
        for (int j = 0; j < 8; j++) {
            ushortt h0 = (ushortt)(bw[2 * j] & 0xffff);
            ushortt h1 = (ushortt)(bw[2 * j + 1] & 0xffff);
            ushortt l0 = (ushortt)(bw[2 * j] >> 16);
            ushortt l1 = (ushortt)(bw[2 * j + 1] >> 16);
            bh[j]  = (uint32_t)h0 | ((uint32_t)h1 << 16);
            blo[j] = (uint32_t)l0 | ((uint32_t)l1 << 16);
        }
        uint32_t boff = base + GB_BH + (uint32_t)tid * 48u;
        *(uint4*)(smem + boff)      = make_uint4(bh[0], bh[1], bh[2], bh[3]);
        *(uint4*)(smem + boff + 16) = make_uint4(bh[4], bh[5], bh[6], bh[7]);
        uint32_t loff = base + GB_BL + (uint32_t)tid * 48u;
        *(uint4*)(smem + loff)      = make_uint4(blo[0], blo[1], blo[2], blo[3]);
        *(uint4*)(smem + loff + 16) = make_uint4(blo[4], blo[5], blo[6], blo[7]);
    };

    const int warp = tid >> 5, lane = tid & 31;
    const int wm = warp & 1, wn = warp >> 1;
    const int g = lane >> 2, tg = lane & 3;
    const uint32_t lrow = (uint32_t)(lane & 15);
    const uint32_t lseg = (uint32_t)(lane >> 4) * 16u;
    const uint32_t brow = (uint32_t)((lane & 7) + ((lane >> 4) << 3));
    const uint32_t bkoff = (uint32_t)(((lane >> 3) & 1) << 3) * 2u;

    float acc[2][8][4];
#pragma unroll
    for (int mf = 0; mf < 2; mf++)
#pragma unroll
        for (int nf = 0; nf < 8; nf++)
#pragma unroll
            for (int ci = 0; ci < 4; ci++) acc[mf][nf][ci] = 0.0f;

    loadT(0);
    for (int t = 0; t < T; t++) {
        int buf = t & 1;
        storeT(buf);
        __syncthreads();
        if (t + 1 < T) loadT(t + 1);
        uint32_t base = su + (uint32_t)buf * GB_BUF;
        unsigned aH[2][4], aL[2][4];
#pragma unroll
        for (int mf = 0; mf < 2; mf++) {
            uint32_t ra = base + (uint32_t)(wm * 32 + mf * 16) * 48u + lrow * 48u + lseg;
            ldm4(aH[mf][0], aH[mf][1], aH[mf][2], aH[mf][3], ra);
            ldm4(aL[mf][0], aL[mf][1], aL[mf][2], aL[mf][3], ra + GB_AL);
        }
#pragma unroll
        for (int np = 0; np < 4; np++) {
            uint32_t rb = base + GB_BH + (uint32_t)(wn * 64 + np * 16) * 48u +
                          brow * 48u + bkoff;
            unsigned bh0, bh1, bh2, bh3, bl0, bl1, bl2, bl3;
            ldm4(bh0, bh1, bh2, bh3, rb);
            ldm4(bl0, bl1, bl2, bl3, rb + (GB_BL - GB_BH));
            int nf0 = np * 2, nf1 = np * 2 + 1;
#pragma unroll
            for (int mf = 0; mf < 2; mf++) mma_bf16(acc[mf][nf0], aH[mf], bh0, bh1);
#pragma unroll
            for (int mf = 0; mf < 2; mf++) mma_bf16(acc[mf][nf1], aH[mf], bh2, bh3);
#pragma unroll
            for (int mf = 0; mf < 2; mf++) mma_bf16(acc[mf][nf0], aH[mf], bl0, bl1);
#pragma unroll
            for (int mf = 0; mf < 2; mf++) mma_bf16(acc[mf][nf1], aH[mf], bl2, bl3);
#pragma unroll
            for (int mf = 0; mf < 2; mf++) mma_bf16(acc[mf][nf0], aL[mf], bh0, bh1);
#pragma unroll
            for (int mf = 0; mf < 2; mf++) mma_bf16(acc[mf][nf1], aL[mf], bh2, bh3);
        }
    }
#pragma unroll
    for (int nf = 0; nf < 8; nf++) {
        int col = wn * 64 + nf * 8 + tg * 2;
        float bv0 = bias[col], bv1 = bias[col + 1];
#pragma unroll
        for (int mf = 0; mf < 2; mf++) {
            int row0 = m0 + wm * 32 + mf * 16 + g;
            *(float2*)&Cf[(size_t)row0 * HID + col] =
                make_float2(acc[mf][nf][0] + bv0, acc[mf][nf][1] + bv1);
            *(float2*)&Cf[(size_t)(row0 + 8) * HID + col] =
                make_float2(acc[mf][nf][2] + bv0, acc[mf][nf][3] + bv1);
        }
    }
}

// ---------------- fused MLP: layers 1-3 + w4 projection, 64 rows/CTA ----------
// smem: ActH 0 (64x528B=33792), ActL 33792, BH 67584 (256x48=12288), BL 79872,
//       sw0t 92160 (4KB) -> total 96256. 2 CTAs/SM.
#define AC_STRIDE 528u
#define AC_L   33792u
#define MB_BH  67584u
#define MB_BL  79872u
#define MB_W0T 92160u
#define MSM_TOT 96256
__global__ void __launch_bounds__(256, 2)
k_mlp(const float* __restrict__ Tt, const uint32_t* __restrict__ Wp,
      const float* __restrict__ b1, const float* __restrict__ b2,
      const float* __restrict__ b3, const float* __restrict__ w0tail,
      const float* __restrict__ w4, float* __restrict__ WP) {
    extern __shared__ __align__(16) char smem[];
    const uint32_t su = smem_u32(smem);
    float* sw0t = (float*)(smem + MB_W0T);

    const int tid = threadIdx.x;
    const int m0 = blockIdx.x * 64;
    const int arow = tid >> 2, aq = tid & 3;

    for (int i = tid; i < 4 * HID; i += 256) sw0t[i] = w0tail[i];
    const int src = g_rowsrc[m0 + arow];
    const float* tp = &g_tail[(size_t)(m0 + arow) * 4];
    const float t0f = tp[0], t1f = tp[1], t2f = tp[2], t3f = tp[3];
    __syncthreads();

    // ---- prologue: act = relu(T[src] + tail·w0tail), packsplit into planes ----
    for (int kc = 0; kc < 16; kc++) {
        float4 f = *(const float4*)(Tt + (size_t)src * HID + kc * 16 + aq * 4);
        float vv[4] = {f.x, f.y, f.z, f.w};
        uint32_t hw[2], lw[2];
#pragma unroll
        for (int j = 0; j < 2; j++) {
            float v0, v1;
            {
                int c0 = kc * 16 + aq * 4 + 2 * j;
                v0 = fmaxf(vv[2 * j] + t0f * sw0t[c0] + t1f * sw0t[HID + c0]
                           + t2f * sw0t[2 * HID + c0] + t3f * sw0t[3 * HID + c0], 0.0f);
                int c1 = c0 + 1;
                v1 = fmaxf(vv[2 * j + 1] + t0f * sw0t[c1] + t1f * sw0t[HID + c1]
                           + t2f * sw0t[2 * HID + c1] + t3f * sw0t[3 * HID + c1], 0.0f);
            }
            ushortt h0 = f2b(v0), h1 = f2b(v1);
            ushortt l0 = f2b(v0 - b2f(h0)), l1 = f2b(v1 - b2f(h1));
            hw[j] = (uint32_t)h0 | ((uint32_t)h1 << 16);
            lw[j] = (uint32_t)l0 | ((uint32_t)l1 << 16);
        }
        uint32_t aoff = (uint32_t)arow * AC_STRIDE + (uint32_t)kc * 32u + (uint32_t)aq * 8u;
        *(uint2*)(smem + aoff)        = make_uint2(hw[0], hw[1]);
        *(uint2*)(smem + aoff + AC_L) = make_uint2(lw[0], lw[1]);
    }

    const int warp = tid >> 5, lane = tid & 31;
    const int wm = warp & 1, wn = warp >> 1;       // 2 x 4, warp tile 32x64
    const int g = lane >> 2, tg = lane & 3;
    const uint32_t lrow = (uint32_t)(lane & 15);
    const uint32_t lseg = (uint32_t)(lane >> 4) * 16u;
    const uint32_t brow = (uint32_t)((lane & 7) + ((lane >> 4) << 3));
    const uint32_t bkoff = (uint32_t)(((lane >> 3) & 1) << 3) * 2u;

    float acc[2][8][4];
    uint32_t bw[16];

    for (int layer = 0; layer < 3; layer++) {
        const uint32_t* W = Wp + (size_t)layer * HID * HID;
        const float* bias = (layer == 0) ? b1 : (layer == 1) ? b2 : b3;
#pragma unroll
        for (int mf = 0; mf < 2; mf++)
#pragma unroll
            for (int nf = 0; nf < 8; nf++)
#pragma unroll
                for (int ci = 0; ci < 4; ci++) acc[mf][nf][ci] = 0.0f;

        for (int t = 0; t < 16; t++) {
#pragma unroll
            for (int r = 0; r < 16; r++) bw[r] = W[(size_t)(t * 16 + r) * HID + tid];
            __syncthreads();   // previous tile's B reads (or prologue act writes) done
            {
                uint32_t bh[8], blo[8];
#pragma unroll
                for (int j = 0; j < 8; j++) {
                    ushortt h0 = (ushortt)(bw[2 * j] & 0xffff);
                    ushortt h1 = (ushortt)(bw[2 * j + 1] & 0xffff);
                    ushortt l0 = (ushortt)(bw[2 * j] >> 16);
                    ushortt l1 = (ushortt)(bw[2 * j + 1] >> 16);
                    bh[j]  = (uint32_t)h0 | ((uint32_t)h1 << 16);
                    blo[j] = (uint32_t)l0 | ((uint32_t)l1 << 16);
                }
                uint32_t boff = MB_BH + (uint32_t)tid * 48u;
                *(uint4*)(smem + boff)      = make_uint4(bh[0], bh[1], bh[2], bh[3]);
                *(uint4*)(smem + boff + 16) = make_uint4(bh[4], bh[5], bh[6], bh[7]);
                uint32_t loff = MB_BL + (uint32_t)tid * 48u;
                *(uint4*)(smem + loff)      = make_uint4(blo[0], blo[1], blo[2], blo[3]);
                *(uint4*)(smem + loff + 16) = make_uint4(blo[4], blo[5], blo[6], blo[7]);
            }
            __syncthreads();

            unsigned aH[2][4], aL[2][4];
#pragma unroll
            for (int mf = 0; mf < 2; mf++) {
                uint32_t ra = su + (uint32_t)(wm * 32 + mf * 16 + (int)lrow) * AC_STRIDE +
                              (uint32_t)t * 32u + lseg;
                ldm4(aH[mf][0], aH[mf][1], aH[mf][2], aH[mf][3], ra);
                ldm4(aL[mf][0], aL[mf][1], aL[mf][2], aL[mf][3], ra + AC_L);
            }
#pragma unroll
            for (int np = 0; np < 4; np++) {
                uint32_t rb = su + MB_BH + (uint32_t)(wn * 64 + np * 16) * 48u +
                              brow * 48u + bkoff;
                unsigned bh0, bh1, bh2, bh3, bl0, bl1, bl2, bl3;
                ldm4(bh0, bh1, bh2, bh3, rb);
                ldm4(bl0, bl1, bl2, bl3, rb + (MB_BL - MB_BH));
                int nf0 = np * 2, nf1 = np * 2 + 1;
#pragma unroll
                for (int mf = 0; mf < 2; mf++) mma_bf16(acc[mf][nf0], aH[mf], bh0, bh1);
#pragma unroll
                for (int mf = 0; mf < 2; mf++) mma_bf16(acc[mf][nf1], aH[mf], bh2, bh3);
#pragma unroll
                for (int mf = 0; mf < 2; mf++) mma_bf16(acc[mf][nf0], aH[mf], bl0, bl1);
#pragma unroll
                for (int mf = 0; mf < 2; mf++) mma_bf16(acc[mf][nf1], aH[mf], bl2, bl3);
#pragma unroll
                for (int mf = 0; mf < 2; mf++) mma_bf16(acc[mf][nf0], aL[mf], bh0, bh1);
#pragma unroll
                for (int mf = 0; mf < 2; mf++) mma_bf16(acc[mf][nf1], aL[mf], bh2, bh3);
            }
        }
        __syncthreads();   // all A reads done before overwriting act planes

        if (layer < 2) {
            // write relu(acc+bias) packsplit back into act planes
#pragma unroll
            for (int nf = 0; nf < 8; nf++) {
                int col = wn * 64 + nf * 8 + tg * 2;
                float bv0 = bias[col], bv1 = bias[col + 1];
#pragma unroll
                for (int mf = 0; mf < 2; mf++) {
                    int r0 = wm * 32 + mf * 16 + g;
                    float v00 = fmaxf(acc[mf][nf][0] + bv0, 0.0f);
                    float v01 = fmaxf(acc[mf][nf][1] + bv1, 0.0f);
                    float v10 = fmaxf(acc[mf][nf][2] + bv0, 0.0f);
                    float v11 = fmaxf(acc[mf][nf][3] + bv1, 0.0f);
                    uint32_t o0 = (uint32_t)r0 * AC_STRIDE + (uint32_t)col * 2u;
                    uint32_t o1 = (uint32_t)(r0 + 8) * AC_STRIDE + (uint32_t)col * 2u;
                    *(uint32_t*)(smem + o0)        = packsplit(v00) & 0xffff |
                                                     ((packsplit(v01) & 0xffff) << 16);
                    // NOTE: hi plane holds (h0|h1<<16); lo plane (l0|l1<<16)
                    ushortt h0 = f2b(v00), h1 = f2b(v01);
                    ushortt l0 = f2b(v00 - b2f(h0)), l1 = f2b(v01 - b2f(h1));
                    *(uint32_t*)(smem + o0)        = (uint32_t)h0 | ((uint32_t)h1 << 16);
                    *(uint32_t*)(smem + o0 + AC_L) = (uint32_t)l0 | ((uint32_t)l1 << 16);
                    ushortt h2 = f2b(v10), h3 = f2b(v11);
                    ushortt l2 = f2b(v10 - b2f(h2)), l3 = f2b(v11 - b2f(h3));
                    *(uint32_t*)(smem + o1)        = (uint32_t)h2 | ((uint32_t)h3 << 16);
                    *(uint32_t*)(smem + o1 + AC_L) = (uint32_t)l2 | ((uint32_t)l3 << 16);
                }
            }
            __syncthreads();
        }
    }

    // ---- projection epilogue (layer3 acc): wp = rwt * relu(acc+b3)·w4 ----
    float* sred = (float*)(smem + MB_BH);          // [4][64][3] = 3KB (B buffer reuse)
    float* w4s  = (float*)(smem + MB_BH + 3072);   // 768 floats
    for (int i = tid; i < HID * 3; i += 256) w4s[i] = w4[i];
    __syncthreads();
    float s[4][3];
#pragma unroll
    for (int i = 0; i < 4; i++) { s[i][0] = 0.f; s[i][1] = 0.f; s[i][2] = 0.f; }
#pragma unroll
    for (int nf = 0; nf < 8; nf++) {
        int col = wn * 64 + nf * 8 + tg * 2;
        float bv0 = b3[col], bv1 = b3[col + 1];
        float w00 = w4s[col * 3 + 0], w01 = w4s[col * 3 + 1], w02 = w4s[col * 3 + 2];
        float w10 = w4s[col * 3 + 3], w11 = w4s[col * 3 + 4], w12 = w4s[col * 3 + 5];
#pragma unroll
        for (int mf = 0; mf < 2; mf++) {
            float v00 = fmaxf(acc[mf][nf][0] + bv0, 0.0f);
            float v01 = fmaxf(acc[mf][nf][1] + bv1, 0.0f);
            float v10 = fmaxf(acc[mf][nf][2] + bv0, 0.0f);
            float v11 = fmaxf(acc[mf][nf][3] + bv1, 0.0f);
            int i0 = mf * 2, i1 = mf * 2 + 1;
            s[i0][0] += v00 * w00 + v01 * w10;
            s[i0][1] += v00 * w01 + v01 * w11;
            s[i0][2] += v00 * w02 + v01 * w12;
            s[i1][0] += v10 * w00 + v11 * w10;
            s[i1][1] += v10 * w01 + v11 * w11;
            s[i1][2] += v10 * w02 + v11 * w12;
        }
    }
#pragma unroll
    for (int i = 0; i < 4; i++)
#pragma unroll
        for (int c = 0; c < 3; c++) {
            s[i][c] += __shfl_xor_sync(0xffffffffu, s[i][c], 1);
            s[i][c] += __shfl_xor_sync(0xffffffffu, s[i][c], 2);
        }
    if (tg == 0) {
#pragma unroll
        for (int mf = 0; mf < 2; mf++)
#pragma unroll
            for (int hh = 0; hh < 2; hh++) {
                int row = wm * 32 + mf * 16 + g + hh * 8;
                int i = mf * 2 + hh;
                sred[(wn * 64 + row) * 3 + 0] = s[i][0];
                sred[(wn * 64 + row) * 3 + 1] = s[i][1];
                sred[(wn * 64 + row) * 3 + 2] = s[i][2];
            }
    }
    __syncthreads();
    for (int i = tid; i < 64 * 3; i += 256) {
        int row = i / 3, c = i % 3;
        float sum = sred[(0 * 64 + row) * 3 + c] + sred[(1 * 64 + row) * 3 + c]
                  + sred[(2 * 64 + row) * 3 + c] + sred[(3 * 64 + row) * 3 + c];
        WP[(size_t)(m0 + row) * 3 + c] = g_rwt[m0 + row] * sum;
    }
}

// ---------------- combine ----------------
__global__ void k_comb(const float* __restrict__ wp, const float* __restrict__ b4,
                       float* __restrict__ out) {
    int q = blockIdx.x * blockDim.x + threadIdx.x;
    if (q >= BQ * NQ) return;
    int pg = g_qpc[q];
    float b40 = b4[0], b41 = b4[1], b42 = b4[2];
    float pa0 = 0.f, pa1 = 0.f, pa2 = 0.f, pl0 = 0.f, pl1 = 0.f, pl2 = 0.f;
#pragma unroll
    for (int k = 0; k < 4; k++) {
        size_t ra = (size_t)(pg * 4 + k) * 3;
        pa0 += wp[ra + 0]; pa1 += wp[ra + 1]; pa2 += wp[ra + 2];
        size_t rl = (size_t)(ATTR + q * 4 + k) * 3;
        pl0 += wp[rl + 0]; pl1 += wp[rl + 1]; pl2 += wp[rl + 2];
    }
    out[(size_t)q * 3 + 0] = 0.5f * (pa0 + b40) + 0.5f * (pl0 + b40);
    out[(size_t)q * 3 + 1] = 0.5f * (pa1 + b41) + 0.5f * (pl1 + b41);
    out[(size_t)q * 3 + 2] = 0.5f * (pa2 + b42) + 0.5f * (pl2 + b42);
}

// ---------------- launch ----------------
extern "C" void kernel_launch(void* const* d_in, const int* in_sizes, int n_in,
                              void* d_out, int out_size) {
    const float* feat  = (const float*)d_in[0];
    const float* attn  = (const float*)d_in[1];
    const float* coord = (const float*)d_in[2];
    const float* cell  = (const float*)d_in[3];
    const float* w0 = (const float*)d_in[4];
    const float* b0 = (const float*)d_in[5];
    const float* w1 = (const float*)d_in[6];
    const float* b1 = (const float*)d_in[7];
    const float* w2 = (const float*)d_in[8];
    const float* b2 = (const float*)d_in[9];
    const float* w3 = (const float*)d_in[10];
    const float* b3 = (const float*)d_in[11];
    const float* w4 = (const float*)d_in[12];
    const float* b4 = (const float*)d_in[13];
    float* out = (float*)d_out;

    float *Tt, *WP;
    uint32_t *W0f, *Wp;
    cudaGetSymbolAddress((void**)&Tt,  g_T);
    cudaGetSymbolAddress((void**)&W0f, g_W0f32);
    cudaGetSymbolAddress((void**)&Wp,  g_Wp32);
    cudaGetSymbolAddress((void**)&WP,  g_wp);
    const float* w0tail = w0 + (size_t)D9 * HID;

    static int once = 0;
    static cudaStream_t s2;
    static cudaEvent_t evF, evJ;
    if (!once) {
        cudaFuncSetAttribute(k_tgemm, cudaFuncAttributeMaxDynamicSharedMemorySize, GSM_TOT);
        cudaFuncSetAttribute(k_mlp,   cudaFuncAttributeMaxDynamicSharedMemorySize, MSM_TOT);
        cudaStreamCreateWithFlags(&s2, cudaStreamNonBlocking);
        cudaEventCreateWithFlags(&evF, cudaEventDisableTiming);
        cudaEventCreateWithFlags(&evJ, cudaEventDisableTiming);
        once = 1;
    }

    // fork: top-k / build chain on s2, weight-prep + T-gemm on main stream
    cudaEventRecord(evF, 0);
    cudaStreamWaitEvent(s2, evF, 0);
    k_argmax<<<(BQ * HWQ + 255) / 256, 256, 0, s2>>>(attn);
    k_top4a<<<BQ * NCHUNK, 256, 0, s2>>>(attn);
    k_top4b<<<1, 256, 0, s2>>>();
    k_build<<<(BQ * HWQ + BQ * NQ + 255) / 256, 256, 0, s2>>>(coord, cell);
    cudaEventRecord(evJ, s2);

    int prepn = D9 * HID + 3 * HID * HID;
    k_prepw<<<(prepn + 255) / 256, 256>>>(w0, w1, w2, w3);
    k_tgemm<<<NPIX / 64, 256, GSM_TOT>>>(feat, W0f, b0, Tt);

    cudaStreamWaitEvent(0, evJ, 0);   // join before fused MLP
    k_mlp<<<NR2 / 64, 256, MSM_TOT>>>(Tt, Wp, b1, b2, b3, w0tail, w4, WP);

    k_comb<<<(BQ * NQ + 255) / 256, 256>>>(WP, b4, out);
}

// round 16
// speedup vs baseline: 1.1846x; 1.0024x over previous
#include <cuda_runtime.h>
#include <cuda_bf16.h>
#include <cstdint>

// ---------------- problem constants ----------------
#define BQ   4
#define DQ   64
#define HQ   64
#define WQ   64
#define HWQ  4096
#define SQ   64
#define NQ   8192
#define KQ   4
#define D9   576
#define HID  256
#define NPIX 16384        // B*HWQ distinct pixel rows
#define ATTR 65536        // attention MLP rows: B*HWQ*4
#define NR2  196608       // ATTR + B*NQ*4 local rows
#define NCHUNK 128

typedef unsigned short ushortt;

// ---------------- device scratch ----------------
__device__ int      g_segm[BQ * HWQ];
__device__ float    g_partv[BQ * NCHUNK * SQ * KQ];
__device__ int      g_parti[BQ * NCHUNK * SQ * KQ];
__device__ float    g_top4v[BQ * SQ * KQ];
__device__ int      g_top4i[BQ * SQ * KQ];
// pre-split, pre-tiled weight planes: [tile][n(256)][8 u32 of (h2k|h2k+1<<16)]
__device__ __align__(16) uint32_t g_W0tH[36 * 2048];
__device__ __align__(16) uint32_t g_W0tL[36 * 2048];
__device__ __align__(16) uint32_t g_WtH[3 * 16 * 2048];
__device__ __align__(16) uint32_t g_WtL[3 * 16 * 2048];
__device__ __align__(16) float    g_T[(size_t)NPIX * HID];   // 16.8MB
__device__ int      g_rowsrc[NR2];
__device__ float    g_tail[(size_t)NR2 * 4];
__device__ float    g_rwt[NR2];
__device__ int      g_qpc[BQ * NQ];
__device__ float    g_wp[(size_t)NR2 * 3];

// ---------------- helpers ----------------
__device__ __forceinline__ ushortt f2b(float x) {
    return __bfloat16_as_ushort(__float2bfloat16_rn(x));
}
__device__ __forceinline__ float b2f(ushortt u) {
    return __bfloat162float(__ushort_as_bfloat16(u));
}
__device__ __forceinline__ uint32_t smem_u32(const void* p) {
    uint32_t a;
    asm("{ .reg .u64 t; cvta.to.shared.u64 t, %1; cvt.u32.u64 %0, t; }" : "=r"(a) : "l"(p));
    return a;
}
__device__ __forceinline__ void mma_bf16(float* c, const unsigned* a,
                                         unsigned b0, unsigned b1) {
    asm volatile(
        "mma.sync.aligned.m16n8k16.row.col.f32.bf16.bf16.f32 "
        "{%0,%1,%2,%3},{%4,%5,%6,%7},{%8,%9},{%0,%1,%2,%3};\n"
        : "+f"(c[0]), "+f"(c[1]), "+f"(c[2]), "+f"(c[3])
        : "r"(a[0]), "r"(a[1]), "r"(a[2]), "r"(a[3]), "r"(b0), "r"(b1));
}
__device__ __forceinline__ void ldm4(unsigned& r0, unsigned& r1, unsigned& r2,
                                     unsigned& r3, uint32_t addr) {
    asm volatile("ldmatrix.sync.aligned.m8n8.x4.shared.b16 {%0,%1,%2,%3}, [%4];"
                 : "=r"(r0), "=r"(r1), "=r"(r2), "=r"(r3) : "r"(addr));
}
// top-4 insertion, lax.top_k tie semantics
__device__ __forceinline__ void ins4(float v[4], int id[4], float val, int p) {
    if (!(val > v[3] || (val == v[3] && p < id[3]))) return;
    int pos = 3;
    while (pos > 0 && (val > v[pos - 1] || (val == v[pos - 1] && p < id[pos - 1]))) pos--;
    for (int q = 3; q > pos; q--) { v[q] = v[q - 1]; id[q] = id[q - 1]; }
    v[pos] = val; id[pos] = p;
}

// ---------------- prep: split + tile weights ----------------
__global__ void k_prepw(const float* __restrict__ w0, const float* __restrict__ w1,
                        const float* __restrict__ w2, const float* __restrict__ w3) {
    int t = blockIdx.x * blockDim.x + threadIdx.x;
    const int n0 = 36 * 2048;      // W0 pairs
    if (t < n0) {
        int tile = t >> 11;
        int rem = t & 2047;
        int n = rem >> 3, j = rem & 7;
        int k0 = tile * 16 + 2 * j;
        float v0 = w0[k0 * HID + n], v1 = w0[(k0 + 1) * HID + n];
        ushortt h0 = f2b(v0), h1 = f2b(v1);
        ushortt l0 = f2b(v0 - b2f(h0)), l1 = f2b(v1 - b2f(h1));
        g_W0tH[t] = (uint32_t)h0 | ((uint32_t)h1 << 16);
        g_W0tL[t] = (uint32_t)l0 | ((uint32_t)l1 << 16);
        return;
    }
    int t2 = t - n0;
    if (t2 >= 3 * 32768) return;
    int layer = t2 >> 15;
    int i = t2 & 32767;
    int tile = i >> 11;
    int rem = i & 2047;
    int n = rem >> 3, j = rem & 7;
    int k0 = tile * 16 + 2 * j;
    const float* w = (layer == 0) ? w1 : (layer == 1) ? w2 : w3;
    float v0 = w[k0 * HID + n], v1 = w[(k0 + 1) * HID + n];
    ushortt h0 = f2b(v0), h1 = f2b(v1);
    ushortt l0 = f2b(v0 - b2f(h0)), l1 = f2b(v1 - b2f(h1));
    g_WtH[t2] = (uint32_t)h0 | ((uint32_t)h1 << 16);
    g_WtL[t2] = (uint32_t)l0 | ((uint32_t)l1 << 16);
}

// ---------------- argmax ----------------
__global__ void k_argmax(const float* __restrict__ attn) {
    int t = blockIdx.x * blockDim.x + threadIdx.x;
    if (t >= BQ * HWQ) return;
    const float* row = attn + (size_t)t * SQ;
    float best = row[0]; int bi = 0;
    for (int s = 1; s < SQ; s++) {
        float v = row[s];
        if (v > best) { best = v; bi = s; }
    }
    g_segm[t] = bi;
}

// ---------------- top4 stage A ----------------
__global__ void k_top4a(const float* __restrict__ attn) {
    __shared__ float tile[32][SQ + 1];
    __shared__ float sv[4][SQ][4];
    __shared__ int   si[4][SQ][4];
    int b = blockIdx.x >> 7;
    int chunk = blockIdx.x & 127;
    int tid = threadIdx.x;
    int s = tid & 63, sub = tid >> 6;
    int p0 = chunk * 32;
    for (int i = tid; i < 32 * SQ; i += 256) {
        int r = i >> 6, c = i & 63;
        tile[r][c] = attn[((size_t)(b * HWQ) + p0 + r) * SQ + c];
    }
    __syncthreads();
    float v[4]  = {-1e30f, -1e30f, -1e30f, -1e30f};
    int   id[4] = {0x7fffffff, 0x7fffffff, 0x7fffffff, 0x7fffffff};
    for (int rr = 0; rr < 8; rr++) {
        int r = sub * 8 + rr;
        ins4(v, id, tile[r][s], p0 + r);
    }
    for (int q = 0; q < 4; q++) { sv[sub][s][q] = v[q]; si[sub][s][q] = id[q]; }
    __syncthreads();
    if (sub == 0) {
        float fv[4]  = {-1e30f, -1e30f, -1e30f, -1e30f};
        int   fi[4]  = {0x7fffffff, 0x7fffffff, 0x7fffffff, 0x7fffffff};
        for (int ss = 0; ss < 4; ss++)
            for (int q = 0; q < 4; q++)
                ins4(fv, fi, sv[ss][s][q], si[ss][s][q]);
        int base = ((b * NCHUNK + chunk) * SQ + s) * 4;
        for (int q = 0; q < 4; q++) { g_partv[base + q] = fv[q]; g_parti[base + q] = fi[q]; }
    }
}

// ---------------- top4 stage B ----------------
__global__ void k_top4b() {
    int t = threadIdx.x;
    int b = t >> 6, s = t & 63;
    float v[4]  = {-1e30f, -1e30f, -1e30f, -1e30f};
    int   id[4] = {0x7fffffff, 0x7fffffff, 0x7fffffff, 0x7fffffff};
    for (int ch = 0; ch < NCHUNK; ch++) {
        int base = ((b * NCHUNK + ch) * SQ + s) * 4;
        for (int q = 0; q < 4; q++) ins4(v, id, g_partv[base + q], g_parti[base + q]);
    }
    int o = (b * SQ + s) * 4;
    for (int q = 0; q < 4; q++) { g_top4v[o + q] = v[q]; g_top4i[o + q] = id[q]; }
}

// ---------------- build ----------------
__global__ void k_build(const float* __restrict__ coord,
                        const float* __restrict__ cell) {
    int t = blockIdx.x * blockDim.x + threadIdx.x;
    if (t < BQ * HWQ) {
        int b = t >> 12;          // HWQ = 4096
        int pc1d = t & 4095;
        int segm = g_segm[b * HWQ + pc1d];
        const float* tv = &g_top4v[(b * SQ + segm) * 4];
        const int*   ti = &g_top4i[(b * SQ + segm) * 4];
        float sum = tv[0] + tv[1] + tv[2] + tv[3];
        size_t cb = (size_t)b * NQ * 2;   // cell uniform per batch
        float rc0 = cell[cb] * (float)HQ, rc1 = cell[cb + 1] * (float)WQ;
        for (int k = 0; k < 4; k++) {
            int rc = ti[k];
            int rrc = rc - pc1d;
            float rel0 = (float)(rrc >> 6) * (1.0f / (float)HQ);
            float rel1 = (float)(rrc & 63) * (1.0f / (float)WQ);
            int rowr = t * 4 + k;
            g_rowsrc[rowr] = rc;             // batch-0 row of T (faithful)
            g_tail[(size_t)rowr * 4 + 0] = rel0;
            g_tail[(size_t)rowr * 4 + 1] = rel1;
            g_tail[(size_t)rowr * 4 + 2] = rc0;
            g_tail[(size_t)rowr * 4 + 3] = rc1;
            g_rwt[rowr] = tv[k] / sum;
        }
        return;
    }
    int q = t - BQ * HWQ;
    if (q >= BQ * NQ) return;
    int b = q >> 13;
    size_t cb = (size_t)q * 2;
    float c0 = coord[cb], c1 = coord[cb + 1];
    float rc0 = cell[cb] * (float)HQ, rc1 = cell[cb + 1] * (float)WQ;

    float pcf0 = (c0 + 1.0f) / 2.0f * (float)HQ;
    float pcf1 = (c1 + 1.0f) / 2.0f * (float)WQ;
    int pc0 = (int)pcf0; pc0 = max(0, min(HWQ - 1, pc0));
    int pc1 = (int)pcf1; pc1 = max(0, min(HWQ - 1, pc1));
    int pc1d = pc0 * HQ + pc1;
    pc1d = max(0, min(HWQ - 1, pc1d));
    g_qpc[q] = b * HWQ + pc1d;

    const float offv[4][2] = {{-1.f, -1.f}, {-1.f, 1.f}, {1.f, -1.f}, {1.f, 1.f}};
    float area[4];
    for (int j = 0; j < 4; j++) {
        float rx = 1.0f / (float)HQ, ry = 1.0f / (float)WQ;
        float cc0 = c0 + offv[j][0] * rx + 1e-6f;
        float cc1 = c1 + offv[j][1] * ry + 1e-6f;
        cc0 = fminf(fmaxf(cc0, -1.0f + 1e-6f), 1.0f - 1e-6f);
        cc1 = fminf(fmaxf(cc1, -1.0f + 1e-6f), 1.0f - 1e-6f);
        float fy = ((cc0 + 1.0f) * (float)HQ - 1.0f) / 2.0f;
        float fx = ((cc1 + 1.0f) * (float)WQ - 1.0f) / 2.0f;
        int iy = (int)rintf(fy); iy = max(0, min(HQ - 1, iy));
        int ix = (int)rintf(fx); ix = max(0, min(WQ - 1, ix));
        int flat = iy * WQ + ix;
        float qc0 = -1.0f + (2.0f * (float)iy + 1.0f) / (float)HQ;
        float qc1 = -1.0f + (2.0f * (float)ix + 1.0f) / (float)WQ;
        float r0 = (c0 - qc0) * (float)HQ;
        float r1 = (c1 - qc1) * (float)WQ;
        int rowr = ATTR + q * 4 + j;
        g_rowsrc[rowr] = b * HWQ + flat;
        g_tail[(size_t)rowr * 4 + 0] = r0;
        g_tail[(size_t)rowr * 4 + 1] = r1;
        g_tail[(size_t)rowr * 4 + 2] = rc0;
        g_tail[(size_t)rowr * 4 + 3] = rc1;
        area[j] = fabsf(r0 * r1) + 1e-9f;
    }
    float tot = area[0] + area[1] + area[2] + area[3];
    for (int j = 0; j < 4; j++) g_rwt[ATTR + q * 4 + j] = area[3 - j] / tot;
}

// ---------------- T-gemm: implicit-unfold conv, BM=64 BN=256 ----------------
#define GB_BUF 30720u
#define GB_AL  3072u
#define GB_BH  6144u
#define GB_BL  18432u
#define GSM_TOT 61440
__global__ void __launch_bounds__(256, 2)
k_tgemm(const float* __restrict__ Af, const float* __restrict__ bias,
        float* __restrict__ Cf) {
    constexpr int T = D9 / 16;
    extern __shared__ __align__(16) char smem[];
    const uint32_t su = smem_u32(smem);
    const int tid = threadIdx.x;
    const int m0 = blockIdx.x * 64;
    const int arow = tid >> 2, aq = tid & 3;
    int p = m0 + arow;
    int fb = p >> 12;
    int pix = p & 4095;
    int fi0 = pix >> 6, fj0 = pix & 63;

    float af[4];
    uint4 bhv0, bhv1, blv0, blv1;
    auto loadT = [&](int t) {
        int kk = t * 16;
#pragma unroll
        for (int j = 0; j < 4; j++) {
            int c9 = kk + aq * 4 + j;
            int c = c9 / 9;
            int r9 = c9 - c * 9;
            int ki = r9 / 3, kj = r9 - (r9 / 3) * 3;
            int ii = fi0 + ki - 1, jj = fj0 + kj - 1;
            float v = 0.0f;
            if ((unsigned)ii < (unsigned)HQ && (unsigned)jj < (unsigned)WQ)
                v = Af[(((size_t)fb * DQ + c) * HQ + ii) * WQ + jj];
            af[j] = v;
        }
        const uint4* ph = (const uint4*)(g_W0tH + ((size_t)t * 256 + tid) * 8);
        bhv0 = ph[0]; bhv1 = ph[1];
        const uint4* pl = (const uint4*)(g_W0tL + ((size_t)t * 256 + tid) * 8);
        blv0 = pl[0]; blv1 = pl[1];
    };
    auto storeT = [&](int buf) {
        uint32_t base = (uint32_t)buf * GB_BUF;
        uint32_t hw[2], lw[2];
#pragma unroll
        for (int j = 0; j < 2; j++) {
            float v0 = af[2 * j], v1 = af[2 * j + 1];
            ushortt h0 = f2b(v0), h1 = f2b(v1);
            ushortt l0 = f2b(v0 - b2f(h0)), l1 = f2b(v1 - b2f(h1));
            hw[j] = (uint32_t)h0 | ((uint32_t)h1 << 16);
            lw[j] = (uint32_t)l0 | ((uint32_t)l1 << 16);
        }
        uint32_t aoff = base + (uint32_t)arow * 48u + (uint32_t)aq * 8u;
        *(uint2*)(smem + aoff)         = make_uint2(hw[0], hw[1]);
        *(uint2*)(smem + aoff + GB_AL) = make_uint2(lw[0], lw[1]);
        uint32_t boff = base + GB_BH + (uint32_t)tid * 48u;
        *(uint4*)(smem + boff)      = bhv0;
        *(uint4*)(smem + boff + 16) = bhv1;
        uint32_t loff = base + GB_BL + (uint32_t)tid * 48u;
        *(uint4*)(smem + loff)      = blv0;
        *(uint4*)(smem + loff + 16) = blv1;
    };

    const int warp = tid >> 5, lane = tid & 31;
    const int wm = warp & 1, wn = warp >> 1;
    const int g = lane >> 2, tg = lane & 3;
    const uint32_t lrow = (uint32_t)(lane & 15);
    const uint32_t lseg = (uint32_t)(lane >> 4) * 16u;
    const uint32_t brow = (uint32_t)((lane & 7) + ((lane >> 4) << 3));
    const uint32_t bkoff = (uint32_t)(((lane >> 3) & 1) << 3) * 2u;

    float acc[2][8][4];
#pragma unroll
    for (int mf = 0; mf < 2; mf++)
#pragma unroll
        for (int nf = 0; nf < 8; nf++)
#pragma unroll
            for (int ci = 0; ci < 4; ci++) acc[mf][nf][ci] = 0.0f;

    loadT(0);
    for (int t = 0; t < T; t++) {
        int buf = t & 1;
        storeT(buf);
        __syncthreads();
        if (t + 1 < T) loadT(t + 1);
        uint32_t base = su + (uint32_t)buf * GB_BUF;
        unsigned aH[2][4], aL[2][4];
#pragma unroll
        for (int mf = 0; mf < 2; mf++) {
            uint32_t ra = base + (uint32_t)(wm * 32 + mf * 16) * 48u + lrow * 48u + lseg;
            ldm4(aH[mf][0], aH[mf][1], aH[mf][2], aH[mf][3], ra);
            ldm4(aL[mf][0], aL[mf][1], aL[mf][2], aL[mf][3], ra + GB_AL);
        }
#pragma unroll
        for (int np = 0; np < 4; np++) {
            uint32_t rb = base + GB_BH + (uint32_t)(wn * 64 + np * 16) * 48u +
                          brow * 48u + bkoff;
            unsigned bh0, bh1, bh2, bh3, bl0, bl1, bl2, bl3;
            ldm4(bh0, bh1, bh2, bh3, rb);
            ldm4(bl0, bl1, bl2, bl3, rb + (GB_BL - GB_BH));
            int nf0 = np * 2, nf1 = np * 2 + 1;
#pragma unroll
            for (int mf = 0; mf < 2; mf++) mma_bf16(acc[mf][nf0], aH[mf], bh0, bh1);
#pragma unroll
            for (int mf = 0; mf < 2; mf++) mma_bf16(acc[mf][nf1], aH[mf], bh2, bh3);
#pragma unroll
            for (int mf = 0; mf < 2; mf++) mma_bf16(acc[mf][nf0], aH[mf], bl0, bl1);
#pragma unroll
            for (int mf = 0; mf < 2; mf++) mma_bf16(acc[mf][nf1], aH[mf], bl2, bl3);
#pragma unroll
            for (int mf = 0; mf < 2; mf++) mma_bf16(acc[mf][nf0], aL[mf], bh0, bh1);
#pragma unroll
            for (int mf = 0; mf < 2; mf++) mma_bf16(acc[mf][nf1], aL[mf], bh2, bh3);
        }
    }
#pragma unroll
    for (int nf = 0; nf < 8; nf++) {
        int col = wn * 64 + nf * 8 + tg * 2;
        float bv0 = bias[col], bv1 = bias[col + 1];
#pragma unroll
        for (int mf = 0; mf < 2; mf++) {
            int row0 = m0 + wm * 32 + mf * 16 + g;
            *(float2*)&Cf[(size_t)row0 * HID + col] =
                make_float2(acc[mf][nf][0] + bv0, acc[mf][nf][1] + bv1);
            *(float2*)&Cf[(size_t)(row0 + 8) * HID + col] =
                make_float2(acc[mf][nf][2] + bv0, acc[mf][nf][3] + bv1);
        }
    }
}

// ---------------- fused MLP: layers 1-3 + w4 projection, 64 rows/CTA ----------
#define AC_STRIDE 528u
#define AC_L   33792u
#define MB_BH  67584u
#define MB_BL  79872u
#define MB_W0T 92160u
#define MSM_TOT 96256
__global__ void __launch_bounds__(256, 2)
k_mlp(const float* __restrict__ Tt,
      const float* __restrict__ b1, const float* __restrict__ b2,
      const float* __restrict__ b3, const float* __restrict__ w0tail,
      const float* __restrict__ w4, float* __restrict__ WP) {
    extern __shared__ __align__(16) char smem[];
    const uint32_t su = smem_u32(smem);
    float* sw0t = (float*)(smem + MB_W0T);

    const int tid = threadIdx.x;
    const int m0 = blockIdx.x * 64;
    const int arow = tid >> 2, aq = tid & 3;

    for (int i = tid; i < 4 * HID; i += 256) sw0t[i] = w0tail[i];
    const int src = g_rowsrc[m0 + arow];
    const float* tp = &g_tail[(size_t)(m0 + arow) * 4];
    const float t0f = tp[0], t1f = tp[1], t2f = tp[2], t3f = tp[3];
    __syncthreads();

    // ---- prologue: act = relu(T[src] + tail·w0tail), packsplit into planes ----
    for (int kc = 0; kc < 16; kc++) {
        float4 f = *(const float4*)(Tt + (size_t)src * HID + kc * 16 + aq * 4);
        float vv[4] = {f.x, f.y, f.z, f.w};
        uint32_t hw[2], lw[2];
#pragma unroll
        for (int j = 0; j < 2; j++) {
            int c0 = kc * 16 + aq * 4 + 2 * j;
            int c1 = c0 + 1;
            float v0 = fmaxf(vv[2 * j] + t0f * sw0t[c0] + t1f * sw0t[HID + c0]
                       + t2f * sw0t[2 * HID + c0] + t3f * sw0t[3 * HID + c0], 0.0f);
            float v1 = fmaxf(vv[2 * j + 1] + t0f * sw0t[c1] + t1f * sw0t[HID + c1]
                       + t2f * sw0t[2 * HID + c1] + t3f * sw0t[3 * HID + c1], 0.0f);
            ushortt h0 = f2b(v0), h1 = f2b(v1);
            ushortt l0 = f2b(v0 - b2f(h0)), l1 = f2b(v1 - b2f(h1));
            hw[j] = (uint32_t)h0 | ((uint32_t)h1 << 16);
            lw[j] = (uint32_t)l0 | ((uint32_t)l1 << 16);
        }
        uint32_t aoff = (uint32_t)arow * AC_STRIDE + (uint32_t)kc * 32u + (uint32_t)aq * 8u;
        *(uint2*)(smem + aoff)        = make_uint2(hw[0], hw[1]);
        *(uint2*)(smem + aoff + AC_L) = make_uint2(lw[0], lw[1]);
    }

    const int warp = tid >> 5, lane = tid & 31;
    const int wm = warp & 1, wn = warp >> 1;       // 2 x 4, warp tile 32x64
    const int g = lane >> 2, tg = lane & 3;
    const uint32_t lrow = (uint32_t)(lane & 15);
    const uint32_t lseg = (uint32_t)(lane >> 4) * 16u;
    const uint32_t brow = (uint32_t)((lane & 7) + ((lane >> 4) << 3));
    const uint32_t bkoff = (uint32_t)(((lane >> 3) & 1) << 3) * 2u;

    float acc[2][8][4];
    uint4 mbh0, mbh1, mbl0, mbl1;
    auto loadB = [&](int tt) {
        const uint4* ph = (const uint4*)(g_WtH + ((size_t)tt * 256 + tid) * 8);
        mbh0 = ph[0]; mbh1 = ph[1];
        const uint4* pl = (const uint4*)(g_WtL + ((size_t)tt * 256 + tid) * 8);
        mbl0 = pl[0]; mbl1 = pl[1];
    };
    auto storeB = [&]() {
        uint32_t boff = MB_BH + (uint32_t)tid * 48u;
        *(uint4*)(smem + boff)      = mbh0;
        *(uint4*)(smem + boff + 16) = mbh1;
        uint32_t loff = MB_BL + (uint32_t)tid * 48u;
        *(uint4*)(smem + loff)      = mbl0;
        *(uint4*)(smem + loff + 16) = mbl1;
    };

    loadB(0);
    for (int layer = 0; layer < 3; layer++) {
        const float* bias = (layer == 0) ? b1 : (layer == 1) ? b2 : b3;
#pragma unroll
        for (int mf = 0; mf < 2; mf++)
#pragma unroll
            for (int nf = 0; nf < 8; nf++)
#pragma unroll
                for (int ci = 0; ci < 4; ci++) acc[mf][nf][ci] = 0.0f;

        for (int t = 0; t < 16; t++) {
            int tt = layer * 16 + t;
            __syncthreads();   // prev compute / act writes done
            storeB();
            __syncthreads();
            if (tt + 1 < 48) loadB(tt + 1);    // prefetch under compute

            unsigned aH[2][4], aL[2][4];
#pragma unroll
            for (int mf = 0; mf < 2; mf++) {
                uint32_t ra = su + (uint32_t)(wm * 32 + mf * 16 + (int)lrow) * AC_STRIDE +
                              (uint32_t)t * 32u + lseg;
                ldm4(aH[mf][0], aH[mf][1], aH[mf][2], aH[mf][3], ra);
                ldm4(aL[mf][0], aL[mf][1], aL[mf][2], aL[mf][3], ra + AC_L);
            }
#pragma unroll
            for (int np = 0; np < 4; np++) {
                uint32_t rb = su + MB_BH + (uint32_t)(wn * 64 + np * 16) * 48u +
                              brow * 48u + bkoff;
                unsigned bh0, bh1, bh2, bh3, bl0, bl1, bl2, bl3;
                ldm4(bh0, bh1, bh2, bh3, rb);
                ldm4(bl0, bl1, bl2, bl3, rb + (MB_BL - MB_BH));
                int nf0 = np * 2, nf1 = np * 2 + 1;
#pragma unroll
                for (int mf = 0; mf < 2; mf++) mma_bf16(acc[mf][nf0], aH[mf], bh0, bh1);
#pragma unroll
                for (int mf = 0; mf < 2; mf++) mma_bf16(acc[mf][nf1], aH[mf], bh2, bh3);
#pragma unroll
                for (int mf = 0; mf < 2; mf++) mma_bf16(acc[mf][nf0], aH[mf], bl0, bl1);
#pragma unroll
                for (int mf = 0; mf < 2; mf++) mma_bf16(acc[mf][nf1], aH[mf], bl2, bl3);
#pragma unroll
                for (int mf = 0; mf < 2; mf++) mma_bf16(acc[mf][nf0], aL[mf], bh0, bh1);
#pragma unroll
                for (int mf = 0; mf < 2; mf++) mma_bf16(acc[mf][nf1], aL[mf], bh2, bh3);
            }
        }
        __syncthreads();   // all A reads done before overwriting act planes

        if (layer < 2) {
#pragma unroll
            for (int nf = 0; nf < 8; nf++) {
                int col = wn * 64 + nf * 8 + tg * 2;
                float bv0 = bias[col], bv1 = bias[col + 1];
#pragma unroll
                for (int mf = 0; mf < 2; mf++) {
                    int r0 = wm * 32 + mf * 16 + g;
                    float v00 = fmaxf(acc[mf][nf][0] + bv0, 0.0f);
                    float v01 = fmaxf(acc[mf][nf][1] + bv1, 0.0f);
                    float v10 = fmaxf(acc[mf][nf][2] + bv0, 0.0f);
                    float v11 = fmaxf(acc[mf][nf][3] + bv1, 0.0f);
                    uint32_t o0 = (uint32_t)r0 * AC_STRIDE + (uint32_t)col * 2u;
                    uint32_t o1 = (uint32_t)(r0 + 8) * AC_STRIDE + (uint32_t)col * 2u;
                    ushortt h0 = f2b(v00), h1 = f2b(v01);
                    ushortt l0 = f2b(v00 - b2f(h0)), l1 = f2b(v01 - b2f(h1));
                    *(uint32_t*)(smem + o0)        = (uint32_t)h0 | ((uint32_t)h1 << 16);
                    *(uint32_t*)(smem + o0 + AC_L) = (uint32_t)l0 | ((uint32_t)l1 << 16);
                    ushortt h2 = f2b(v10), h3 = f2b(v11);
                    ushortt l2 = f2b(v10 - b2f(h2)), l3 = f2b(v11 - b2f(h3));
                    *(uint32_t*)(smem + o1)        = (uint32_t)h2 | ((uint32_t)h3 << 16);
                    *(uint32_t*)(smem + o1 + AC_L) = (uint32_t)l2 | ((uint32_t)l3 << 16);
                }
            }
        }
    }

    // ---- projection epilogue (layer3 acc): wp = rwt * relu(acc+b3)·w4 ----
    float* sred = (float*)(smem + MB_BH);          // [4][64][3] = 3KB (B buffer reuse)
    float* w4s  = (float*)(smem + MB_BH + 3072);   // 768 floats
    for (int i = tid; i < HID * 3; i += 256) w4s[i] = w4[i];
    __syncthreads();
    float s[4][3];
#pragma unroll
    for (int i = 0; i < 4; i++) { s[i][0] = 0.f; s[i][1] = 0.f; s[i][2] = 0.f; }
#pragma unroll
    for (int nf = 0; nf < 8; nf++) {
        int col = wn * 64 + nf * 8 + tg * 2;
        float bv0 = b3[col], bv1 = b3[col + 1];
        float w00 = w4s[col * 3 + 0], w01 = w4s[col * 3 + 1], w02 = w4s[col * 3 + 2];
        float w10 = w4s[col * 3 + 3], w11 = w4s[col * 3 + 4], w12 = w4s[col * 3 + 5];
#pragma unroll
        for (int mf = 0; mf < 2; mf++) {
            float v00 = fmaxf(acc[mf][nf][0] + bv0, 0.0f);
            float v01 = fmaxf(acc[mf][nf][1] + bv1, 0.0f);
            float v10 = fmaxf(acc[mf][nf][2] + bv0, 0.0f);
            float v11 = fmaxf(acc[mf][nf][3] + bv1, 0.0f);
            int i0 = mf * 2, i1 = mf * 2 + 1;
            s[i0][0] += v00 * w00 + v01 * w10;
            s[i0][1] += v00 * w01 + v01 * w11;
            s[i0][2] += v00 * w02 + v01 * w12;
            s[i1][0] += v10 * w00 + v11 * w10;
            s[i1][1] += v10 * w01 + v11 * w11;
            s[i1][2] += v10 * w02 + v11 * w12;
        }
    }
#pragma unroll
    for (int i = 0; i < 4; i++)
#pragma unroll
        for (int c = 0; c < 3; c++) {
            s[i][c] += __shfl_xor_sync(0xffffffffu, s[i][c], 1);
            s[i][c] += __shfl_xor_sync(0xffffffffu, s[i][c], 2);
        }
    if (tg == 0) {
#pragma unroll
        for (int mf = 0; mf < 2; mf++)
#pragma unroll
            for (int hh = 0; hh < 2; hh++) {
                int row = wm * 32 + mf * 16 + g + hh * 8;
                int i = mf * 2 + hh;
                sred[(wn * 64 + row) * 3 + 0] = s[i][0];
                sred[(wn * 64 + row) * 3 + 1] = s[i][1];
                sred[(wn * 64 + row) * 3 + 2] = s[i][2];
            }
    }
    __syncthreads();
    for (int i = tid; i < 64 * 3; i += 256) {
        int row = i / 3, c = i % 3;
        float sum = sred[(0 * 64 + row) * 3 + c] + sred[(1 * 64 + row) * 3 + c]
                  + sred[(2 * 64 + row) * 3 + c] + sred[(3 * 64 + row) * 3 + c];
        WP[(size_t)(m0 + row) * 3 + c] = g_rwt[m0 + row] * sum;
    }
}

// ---------------- combine ----------------
__global__ void k_comb(const float* __restrict__ wp, const float* __restrict__ b4,
                       float* __restrict__ out) {
    int q = blockIdx.x * blockDim.x + threadIdx.x;
    if (q >= BQ * NQ) return;
    int pg = g_qpc[q];
    float b40 = b4[0], b41 = b4[1], b42 = b4[2];
    float pa0 = 0.f, pa1 = 0.f, pa2 = 0.f, pl0 = 0.f, pl1 = 0.f, pl2 = 0.f;
#pragma unroll
    for (int k = 0; k < 4; k++) {
        size_t ra = (size_t)(pg * 4 + k) * 3;
        pa0 += wp[ra + 0]; pa1 += wp[ra + 1]; pa2 += wp[ra + 2];
        size_t rl = (size_t)(ATTR + q * 4 + k) * 3;
        pl0 += wp[rl + 0]; pl1 += wp[rl + 1]; pl2 += wp[rl + 2];
    }
    out[(size_t)q * 3 + 0] = 0.5f * (pa0 + b40) + 0.5f * (pl0 + b40);
    out[(size_t)q * 3 + 1] = 0.5f * (pa1 + b41) + 0.5f * (pl1 + b41);
    out[(size_t)q * 3 + 2] = 0.5f * (pa2 + b42) + 0.5f * (pl2 + b42);
}

// ---------------- launch ----------------
extern "C" void kernel_launch(void* const* d_in, const int* in_sizes, int n_in,
                              void* d_out, int out_size) {
    const float* feat  = (const float*)d_in[0];
    const float* attn  = (const float*)d_in[1];
    const float* coord = (const float*)d_in[2];
    const float* cell  = (const float*)d_in[3];
    const float* w0 = (const float*)d_in[4];
    const float* b0 = (const float*)d_in[5];
    const float* w1 = (const float*)d_in[6];
    const float* b1 = (const float*)d_in[7];
    const float* w2 = (const float*)d_in[8];
    const float* b2 = (const float*)d_in[9];
    const float* w3 = (const float*)d_in[10];
    const float* b3 = (const float*)d_in[11];
    const float* w4 = (const float*)d_in[12];
    const float* b4 = (const float*)d_in[13];
    float* out = (float*)d_out;

    float *Tt, *WP;
    cudaGetSymbolAddress((void**)&Tt, g_T);
    cudaGetSymbolAddress((void**)&WP, g_wp);
    const float* w0tail = w0 + (size_t)D9 * HID;

    static int once = 0;
    static cudaStream_t s2;
    static cudaEvent_t evF, evJ;
    if (!once) {
        cudaFuncSetAttribute(k_tgemm, cudaFuncAttributeMaxDynamicSharedMemorySize, GSM_TOT);
        cudaFuncSetAttribute(k_mlp,   cudaFuncAttributeMaxDynamicSharedMemorySize, MSM_TOT);
        cudaStreamCreateWithFlags(&s2, cudaStreamNonBlocking);
        cudaEventCreateWithFlags(&evF, cudaEventDisableTiming);
        cudaEventCreateWithFlags(&evJ, cudaEventDisableTiming);
        once = 1;
    }

    // fork: top-k / build chain on s2, weight-prep + T-gemm on main stream
    cudaEventRecord(evF, 0);
    cudaStreamWaitEvent(s2, evF, 0);
    k_argmax<<<(BQ * HWQ + 255) / 256, 256, 0, s2>>>(attn);
    k_top4a<<<BQ * NCHUNK, 256, 0, s2>>>(attn);
    k_top4b<<<1, 256, 0, s2>>>();
    k_build<<<(BQ * HWQ + BQ * NQ + 255) / 256, 256, 0, s2>>>(coord, cell);
    cudaEventRecord(evJ, s2);

    int prepn = 36 * 2048 + 3 * 32768;
    k_prepw<<<(prepn + 255) / 256, 256>>>(w0, w1, w2, w3);
    k_tgemm<<<NPIX / 64, 256, GSM_TOT>>>(feat, b0, Tt);

    cudaStreamWaitEvent(0, evJ, 0);   // join before fused MLP
    k_mlp<<<NR2 / 64, 256, MSM_TOT>>>(Tt, b1, b2, b3, w0tail, w4, WP);

    k_comb<<<(BQ * NQ + 255) / 256, 256>>>(WP, b4, out);
}

// round 17
// speedup vs baseline: 1.4776x; 1.2473x over previous
#include <cuda_runtime.h>
#include <cuda_fp16.h>
#include <cstdint>

// ---------------- problem constants ----------------
#define BQ   4
#define DQ   64
#define HQ   64
#define WQ   64
#define HWQ  4096
#define SQ   64
#define NQ   8192
#define KQ   4
#define D9   576
#define HID  256
#define NPIX 16384        // B*HWQ distinct pixel rows
#define ATTR 65536        // attention MLP rows: B*HWQ*4
#define NR2  196608       // ATTR + B*NQ*4 local rows
#define NCHUNK 128

typedef unsigned short ushortt;

// ---------------- device scratch ----------------
__device__ int      g_segm[BQ * HWQ];
__device__ float    g_partv[BQ * NCHUNK * SQ * KQ];
__device__ int      g_parti[BQ * NCHUNK * SQ * KQ];
__device__ float    g_top4v[BQ * SQ * KQ];
__device__ int      g_top4i[BQ * SQ * KQ];
// pre-split, pre-tiled fp16 weight planes: [tile][n(256)][8 u32 of (h2k|h2k+1<<16)]
__device__ __align__(16) uint32_t g_W0tH[36 * 2048];
__device__ __align__(16) uint32_t g_W0tL[36 * 2048];
__device__ __align__(16) uint32_t g_WtH[3 * 16 * 2048];
__device__ __align__(16) uint32_t g_WtL[3 * 16 * 2048];
__device__ __align__(16) float    g_T[(size_t)NPIX * HID];   // 16.8MB
__device__ int      g_rowsrc[NR2];
__device__ float    g_tail[(size_t)NR2 * 4];
__device__ float    g_rwt[NR2];
__device__ int      g_qpc[BQ * NQ];
__device__ float    g_wp[(size_t)NR2 * 3];

// ---------------- helpers ----------------
__device__ __forceinline__ ushortt f2h(float x) {
    return __half_as_ushort(__float2half_rn(x));
}
__device__ __forceinline__ float h2f(ushortt u) {
    return __half2float(__ushort_as_half(u));
}
__device__ __forceinline__ uint32_t smem_u32(const void* p) {
    uint32_t a;
    asm("{ .reg .u64 t; cvta.to.shared.u64 t, %1; cvt.u32.u64 %0, t; }" : "=r"(a) : "l"(p));
    return a;
}
__device__ __forceinline__ void mma_f16(float* c, const unsigned* a,
                                        unsigned b0, unsigned b1) {
    asm volatile(
        "mma.sync.aligned.m16n8k16.row.col.f32.f16.f16.f32 "
        "{%0,%1,%2,%3},{%4,%5,%6,%7},{%8,%9},{%0,%1,%2,%3};\n"
        : "+f"(c[0]), "+f"(c[1]), "+f"(c[2]), "+f"(c[3])
        : "r"(a[0]), "r"(a[1]), "r"(a[2]), "r"(a[3]), "r"(b0), "r"(b1));
}
__device__ __forceinline__ void ldm4(unsigned& r0, unsigned& r1, unsigned& r2,
                                     unsigned& r3, uint32_t addr) {
    asm volatile("ldmatrix.sync.aligned.m8n8.x4.shared.b16 {%0,%1,%2,%3}, [%4];"
                 : "=r"(r0), "=r"(r1), "=r"(r2), "=r"(r3) : "r"(addr));
}
// top-4 insertion, lax.top_k tie semantics
__device__ __forceinline__ void ins4(float v[4], int id[4], float val, int p) {
    if (!(val > v[3] || (val == v[3] && p < id[3]))) return;
    int pos = 3;
    while (pos > 0 && (val > v[pos - 1] || (val == v[pos - 1] && p < id[pos - 1]))) pos--;
    for (int q = 3; q > pos; q--) { v[q] = v[q - 1]; id[q] = id[q - 1]; }
    v[pos] = val; id[pos] = p;
}

// ---------------- prep: split + tile weights (fp16 2-term) ----------------
__global__ void k_prepw(const float* __restrict__ w0, const float* __restrict__ w1,
                        const float* __restrict__ w2, const float* __restrict__ w3) {
    int t = blockIdx.x * blockDim.x + threadIdx.x;
    const int n0 = 36 * 2048;
    if (t < n0) {
        int tile = t >> 11;
        int rem = t & 2047;
        int n = rem >> 3, j = rem & 7;
        int k0 = tile * 16 + 2 * j;
        float v0 = w0[k0 * HID + n], v1 = w0[(k0 + 1) * HID + n];
        ushortt h0 = f2h(v0), h1 = f2h(v1);
        ushortt l0 = f2h(v0 - h2f(h0)), l1 = f2h(v1 - h2f(h1));
        g_W0tH[t] = (uint32_t)h0 | ((uint32_t)h1 << 16);
        g_W0tL[t] = (uint32_t)l0 | ((uint32_t)l1 << 16);
        return;
    }
    int t2 = t - n0;
    if (t2 >= 3 * 32768) return;
    int layer = t2 >> 15;
    int i = t2 & 32767;
    int tile = i >> 11;
    int rem = i & 2047;
    int n = rem >> 3, j = rem & 7;
    int k0 = tile * 16 + 2 * j;
    const float* w = (layer == 0) ? w1 : (layer == 1) ? w2 : w3;
    float v0 = w[k0 * HID + n], v1 = w[(k0 + 1) * HID + n];
    ushortt h0 = f2h(v0), h1 = f2h(v1);
    ushortt l0 = f2h(v0 - h2f(h0)), l1 = f2h(v1 - h2f(h1));
    g_WtH[t2] = (uint32_t)h0 | ((uint32_t)h1 << 16);
    g_WtL[t2] = (uint32_t)l0 | ((uint32_t)l1 << 16);
}

// ---------------- argmax ----------------
__global__ void k_argmax(const float* __restrict__ attn) {
    int t = blockIdx.x * blockDim.x + threadIdx.x;
    if (t >= BQ * HWQ) return;
    const float* row = attn + (size_t)t * SQ;
    float best = row[0]; int bi = 0;
    for (int s = 1; s < SQ; s++) {
        float v = row[s];
        if (v > best) { best = v; bi = s; }
    }
    g_segm[t] = bi;
}

// ---------------- top4 stage A ----------------
__global__ void k_top4a(const float* __restrict__ attn) {
    __shared__ float tile[32][SQ + 1];
    __shared__ float sv[4][SQ][4];
    __shared__ int   si[4][SQ][4];
    int b = blockIdx.x >> 7;
    int chunk = blockIdx.x & 127;
    int tid = threadIdx.x;
    int s = tid & 63, sub = tid >> 6;
    int p0 = chunk * 32;
    for (int i = tid; i < 32 * SQ; i += 256) {
        int r = i >> 6, c = i & 63;
        tile[r][c] = attn[((size_t)(b * HWQ) + p0 + r) * SQ + c];
    }
    __syncthreads();
    float v[4]  = {-1e30f, -1e30f, -1e30f, -1e30f};
    int   id[4] = {0x7fffffff, 0x7fffffff, 0x7fffffff, 0x7fffffff};
    for (int rr = 0; rr < 8; rr++) {
        int r = sub * 8 + rr;
        ins4(v, id, tile[r][s], p0 + r);
    }
    for (int q = 0; q < 4; q++) { sv[sub][s][q] = v[q]; si[sub][s][q] = id[q]; }
    __syncthreads();
    if (sub == 0) {
        float fv[4]  = {-1e30f, -1e30f, -1e30f, -1e30f};
        int   fi[4]  = {0x7fffffff, 0x7fffffff, 0x7fffffff, 0x7fffffff};
        for (int ss = 0; ss < 4; ss++)
            for (int q = 0; q < 4; q++)
                ins4(fv, fi, sv[ss][s][q], si[ss][s][q]);
        int base = ((b * NCHUNK + chunk) * SQ + s) * 4;
        for (int q = 0; q < 4; q++) { g_partv[base + q] = fv[q]; g_parti[base + q] = fi[q]; }
    }
}

// ---------------- top4 stage B ----------------
__global__ void k_top4b() {
    int t = threadIdx.x;
    int b = t >> 6, s = t & 63;
    float v[4]  = {-1e30f, -1e30f, -1e30f, -1e30f};
    int   id[4] = {0x7fffffff, 0x7fffffff, 0x7fffffff, 0x7fffffff};
    for (int ch = 0; ch < NCHUNK; ch++) {
        int base = ((b * NCHUNK + ch) * SQ + s) * 4;
        for (int q = 0; q < 4; q++) ins4(v, id, g_partv[base + q], g_parti[base + q]);
    }
    int o = (b * SQ + s) * 4;
    for (int q = 0; q < 4; q++) { g_top4v[o + q] = v[q]; g_top4i[o + q] = id[q]; }
}

// ---------------- build ----------------
__global__ void k_build(const float* __restrict__ coord,
                        const float* __restrict__ cell) {
    int t = blockIdx.x * blockDim.x + threadIdx.x;
    if (t < BQ * HWQ) {
        int b = t >> 12;          // HWQ = 4096
        int pc1d = t & 4095;
        int segm = g_segm[b * HWQ + pc1d];
        const float* tv = &g_top4v[(b * SQ + segm) * 4];
        const int*   ti = &g_top4i[(b * SQ + segm) * 4];
        float sum = tv[0] + tv[1] + tv[2] + tv[3];
        size_t cb = (size_t)b * NQ * 2;   // cell uniform per batch
        float rc0 = cell[cb] * (float)HQ, rc1 = cell[cb + 1] * (float)WQ;
        for (int k = 0; k < 4; k++) {
            int rc = ti[k];
            int rrc = rc - pc1d;
            float rel0 = (float)(rrc >> 6) * (1.0f / (float)HQ);
            float rel1 = (float)(rrc & 63) * (1.0f / (float)WQ);
            int rowr = t * 4 + k;
            g_rowsrc[rowr] = rc;             // batch-0 row of T (faithful)
            g_tail[(size_t)rowr * 4 + 0] = rel0;
            g_tail[(size_t)rowr * 4 + 1] = rel1;
            g_tail[(size_t)rowr * 4 + 2] = rc0;
            g_tail[(size_t)rowr * 4 + 3] = rc1;
            g_rwt[rowr] = tv[k] / sum;
        }
        return;
    }
    int q = t - BQ * HWQ;
    if (q >= BQ * NQ) return;
    int b = q >> 13;
    size_t cb = (size_t)q * 2;
    float c0 = coord[cb], c1 = coord[cb + 1];
    float rc0 = cell[cb] * (float)HQ, rc1 = cell[cb + 1] * (float)WQ;

    float pcf0 = (c0 + 1.0f) / 2.0f * (float)HQ;
    float pcf1 = (c1 + 1.0f) / 2.0f * (float)WQ;
    int pc0 = (int)pcf0; pc0 = max(0, min(HWQ - 1, pc0));
    int pc1 = (int)pcf1; pc1 = max(0, min(HWQ - 1, pc1));
    int pc1d = pc0 * HQ + pc1;
    pc1d = max(0, min(HWQ - 1, pc1d));
    g_qpc[q] = b * HWQ + pc1d;

    const float offv[4][2] = {{-1.f, -1.f}, {-1.f, 1.f}, {1.f, -1.f}, {1.f, 1.f}};
    float area[4];
    for (int j = 0; j < 4; j++) {
        float rx = 1.0f / (float)HQ, ry = 1.0f / (float)WQ;
        float cc0 = c0 + offv[j][0] * rx + 1e-6f;
        float cc1 = c1 + offv[j][1] * ry + 1e-6f;
        cc0 = fminf(fmaxf(cc0, -1.0f + 1e-6f), 1.0f - 1e-6f);
        cc1 = fminf(fmaxf(cc1, -1.0f + 1e-6f), 1.0f - 1e-6f);
        float fy = ((cc0 + 1.0f) * (float)HQ - 1.0f) / 2.0f;
        float fx = ((cc1 + 1.0f) * (float)WQ - 1.0f) / 2.0f;
        int iy = (int)rintf(fy); iy = max(0, min(HQ - 1, iy));
        int ix = (int)rintf(fx); ix = max(0, min(WQ - 1, ix));
        int flat = iy * WQ + ix;
        float qc0 = -1.0f + (2.0f * (float)iy + 1.0f) / (float)HQ;
        float qc1 = -1.0f + (2.0f * (float)ix + 1.0f) / (float)WQ;
        float r0 = (c0 - qc0) * (float)HQ;
        float r1 = (c1 - qc1) * (float)WQ;
        int rowr = ATTR + q * 4 + j;
        g_rowsrc[rowr] = b * HWQ + flat;
        g_tail[(size_t)rowr * 4 + 0] = r0;
        g_tail[(size_t)rowr * 4 + 1] = r1;
        g_tail[(size_t)rowr * 4 + 2] = rc0;
        g_tail[(size_t)rowr * 4 + 3] = rc1;
        area[j] = fabsf(r0 * r1) + 1e-9f;
    }
    float tot = area[0] + area[1] + area[2] + area[3];
    for (int j = 0; j < 4; j++) g_rwt[ATTR + q * 4 + j] = area[3 - j] / tot;
}

// ---------------- T-gemm: implicit-unfold conv, A fp16 single-plane ----------
// per buffer: A 0 (64x48=3072), BH 3072 (12288), BL 15360 (12288) -> 27648
#define TG_BUF 27648u
#define TG_BH  3072u
#define TG_BL  15360u
#define TG_TOT 55296
__global__ void __launch_bounds__(256, 2)
k_tgemm(const float* __restrict__ Af, const float* __restrict__ bias,
        float* __restrict__ Cf) {
    constexpr int T = D9 / 16;
    extern __shared__ __align__(16) char smem[];
    const uint32_t su = smem_u32(smem);
    const int tid = threadIdx.x;
    const int m0 = blockIdx.x * 64;
    const int arow = tid >> 2, aq = tid & 3;
    int p = m0 + arow;
    int fb = p >> 12;
    int pix = p & 4095;
    int fi0 = pix >> 6, fj0 = pix & 63;

    float af[4];
    uint4 bhv0, bhv1, blv0, blv1;
    auto loadT = [&](int t) {
        int kk = t * 16;
#pragma unroll
        for (int j = 0; j < 4; j++) {
            int c9 = kk + aq * 4 + j;
            int c = c9 / 9;
            int r9 = c9 - c * 9;
            int ki = r9 / 3, kj = r9 - (r9 / 3) * 3;
            int ii = fi0 + ki - 1, jj = fj0 + kj - 1;
            float v = 0.0f;
            if ((unsigned)ii < (unsigned)HQ && (unsigned)jj < (unsigned)WQ)
                v = Af[(((size_t)fb * DQ + c) * HQ + ii) * WQ + jj];
            af[j] = v;
        }
        const uint4* ph = (const uint4*)(g_W0tH + ((size_t)t * 256 + tid) * 8);
        bhv0 = ph[0]; bhv1 = ph[1];
        const uint4* pl = (const uint4*)(g_W0tL + ((size_t)t * 256 + tid) * 8);
        blv0 = pl[0]; blv1 = pl[1];
    };
    auto storeT = [&](int buf) {
        uint32_t base = (uint32_t)buf * TG_BUF;
        uint32_t hw0 = (uint32_t)f2h(af[0]) | ((uint32_t)f2h(af[1]) << 16);
        uint32_t hw1 = (uint32_t)f2h(af[2]) | ((uint32_t)f2h(af[3]) << 16);
        uint32_t aoff = base + (uint32_t)arow * 48u + (uint32_t)aq * 8u;
        *(uint2*)(smem + aoff) = make_uint2(hw0, hw1);
        uint32_t boff = base + TG_BH + (uint32_t)tid * 48u;
        *(uint4*)(smem + boff)      = bhv0;
        *(uint4*)(smem + boff + 16) = bhv1;
        uint32_t loff = base + TG_BL + (uint32_t)tid * 48u;
        *(uint4*)(smem + loff)      = blv0;
        *(uint4*)(smem + loff + 16) = blv1;
    };

    const int warp = tid >> 5, lane = tid & 31;
    const int wm = warp & 1, wn = warp >> 1;
    const int g = lane >> 2, tg = lane & 3;
    const uint32_t lrow = (uint32_t)(lane & 15);
    const uint32_t lseg = (uint32_t)(lane >> 4) * 16u;
    const uint32_t brow = (uint32_t)((lane & 7) + ((lane >> 4) << 3));
    const uint32_t bkoff = (uint32_t)(((lane >> 3) & 1) << 3) * 2u;

    float acc[2][8][4];
#pragma unroll
    for (int mf = 0; mf < 2; mf++)
#pragma unroll
        for (int nf = 0; nf < 8; nf++)
#pragma unroll
            for (int ci = 0; ci < 4; ci++) acc[mf][nf][ci] = 0.0f;

    loadT(0);
    for (int t = 0; t < T; t++) {
        int buf = t & 1;
        storeT(buf);
        __syncthreads();
        if (t + 1 < T) loadT(t + 1);
        uint32_t base = su + (uint32_t)buf * TG_BUF;
        unsigned aH[2][4];
#pragma unroll
        for (int mf = 0; mf < 2; mf++) {
            uint32_t ra = base + (uint32_t)(wm * 32 + mf * 16) * 48u + lrow * 48u + lseg;
            ldm4(aH[mf][0], aH[mf][1], aH[mf][2], aH[mf][3], ra);
        }
#pragma unroll
        for (int np = 0; np < 4; np++) {
            uint32_t rb = base + TG_BH + (uint32_t)(wn * 64 + np * 16) * 48u +
                          brow * 48u + bkoff;
            unsigned bh0, bh1, bh2, bh3, bl0, bl1, bl2, bl3;
            ldm4(bh0, bh1, bh2, bh3, rb);
            ldm4(bl0, bl1, bl2, bl3, rb + (TG_BL - TG_BH));
            int nf0 = np * 2, nf1 = np * 2 + 1;
#pragma unroll
            for (int mf = 0; mf < 2; mf++) mma_f16(acc[mf][nf0], aH[mf], bh0, bh1);
#pragma unroll
            for (int mf = 0; mf < 2; mf++) mma_f16(acc[mf][nf1], aH[mf], bh2, bh3);
#pragma unroll
            for (int mf = 0; mf < 2; mf++) mma_f16(acc[mf][nf0], aH[mf], bl0, bl1);
#pragma unroll
            for (int mf = 0; mf < 2; mf++) mma_f16(acc[mf][nf1], aH[mf], bl2, bl3);
        }
    }
#pragma unroll
    for (int nf = 0; nf < 8; nf++) {
        int col = wn * 64 + nf * 8 + tg * 2;
        float bv0 = bias[col], bv1 = bias[col + 1];
#pragma unroll
        for (int mf = 0; mf < 2; mf++) {
            int row0 = m0 + wm * 32 + mf * 16 + g;
            *(float2*)&Cf[(size_t)row0 * HID + col] =
                make_float2(acc[mf][nf][0] + bv0, acc[mf][nf][1] + bv1);
            *(float2*)&Cf[(size_t)(row0 + 8) * HID + col] =
                make_float2(acc[mf][nf][2] + bv0, acc[mf][nf][3] + bv1);
        }
    }
}

// ---------------- fused MLP: layers 1-3 + w4 projection, A fp16 single-plane --
// smem: ACT 0 (64x528=33792), BH 33792 (12288), BL 46080 (12288), sw0t 58368 (4KB)
#define AC_STRIDE 528u
#define MB_BH  33792u
#define MB_BL  46080u
#define MB_W0T 58368u
#define MSM_TOT 62464
__global__ void __launch_bounds__(256, 2)
k_mlp(const float* __restrict__ Tt,
      const float* __restrict__ b1, const float* __restrict__ b2,
      const float* __restrict__ b3, const float* __restrict__ w0tail,
      const float* __restrict__ w4, float* __restrict__ WP) {
    extern __shared__ __align__(16) char smem[];
    const uint32_t su = smem_u32(smem);
    float* sw0t = (float*)(smem + MB_W0T);

    const int tid = threadIdx.x;
    const int m0 = blockIdx.x * 64;
    const int arow = tid >> 2, aq = tid & 3;

    for (int i = tid; i < 4 * HID; i += 256) sw0t[i] = w0tail[i];
    const int src = g_rowsrc[m0 + arow];
    const float* tp = &g_tail[(size_t)(m0 + arow) * 4];
    const float t0f = tp[0], t1f = tp[1], t2f = tp[2], t3f = tp[3];
    __syncthreads();

    // ---- prologue: act = fp16(relu(T[src] + tail·w0tail)) ----
    for (int kc = 0; kc < 16; kc++) {
        float4 f = *(const float4*)(Tt + (size_t)src * HID + kc * 16 + aq * 4);
        float vv[4] = {f.x, f.y, f.z, f.w};
        uint32_t hw[2];
#pragma unroll
        for (int j = 0; j < 2; j++) {
            int c0 = kc * 16 + aq * 4 + 2 * j;
            int c1 = c0 + 1;
            float v0 = fmaxf(vv[2 * j] + t0f * sw0t[c0] + t1f * sw0t[HID + c0]
                       + t2f * sw0t[2 * HID + c0] + t3f * sw0t[3 * HID + c0], 0.0f);
            float v1 = fmaxf(vv[2 * j + 1] + t0f * sw0t[c1] + t1f * sw0t[HID + c1]
                       + t2f * sw0t[2 * HID + c1] + t3f * sw0t[3 * HID + c1], 0.0f);
            hw[j] = (uint32_t)f2h(v0) | ((uint32_t)f2h(v1) << 16);
        }
        uint32_t aoff = (uint32_t)arow * AC_STRIDE + (uint32_t)kc * 32u + (uint32_t)aq * 8u;
        *(uint2*)(smem + aoff) = make_uint2(hw[0], hw[1]);
    }

    const int warp = tid >> 5, lane = tid & 31;
    const int wm = warp & 1, wn = warp >> 1;       // 2 x 4, warp tile 32x64
    const int g = lane >> 2, tg = lane & 3;
    const uint32_t lrow = (uint32_t)(lane & 15);
    const uint32_t lseg = (uint32_t)(lane >> 4) * 16u;
    const uint32_t brow = (uint32_t)((lane & 7) + ((lane >> 4) << 3));
    const uint32_t bkoff = (uint32_t)(((lane >> 3) & 1) << 3) * 2u;

    float acc[2][8][4];
    uint4 mbh0, mbh1, mbl0, mbl1;
    auto loadB = [&](int tt) {
        const uint4* ph = (const uint4*)(g_WtH + ((size_t)tt * 256 + tid) * 8);
        mbh0 = ph[0]; mbh1 = ph[1];
        const uint4* pl = (const uint4*)(g_WtL + ((size_t)tt * 256 + tid) * 8);
        mbl0 = pl[0]; mbl1 = pl[1];
    };
    auto storeB = [&]() {
        uint32_t boff = MB_BH + (uint32_t)tid * 48u;
        *(uint4*)(smem + boff)      = mbh0;
        *(uint4*)(smem + boff + 16) = mbh1;
        uint32_t loff = MB_BL + (uint32_t)tid * 48u;
        *(uint4*)(smem + loff)      = mbl0;
        *(uint4*)(smem + loff + 16) = mbl1;
    };

    loadB(0);
    for (int layer = 0; layer < 3; layer++) {
        const float* bias = (layer == 0) ? b1 : (layer == 1) ? b2 : b3;
#pragma unroll
        for (int mf = 0; mf < 2; mf++)
#pragma unroll
            for (int nf = 0; nf < 8; nf++)
#pragma unroll
                for (int ci = 0; ci < 4; ci++) acc[mf][nf][ci] = 0.0f;

        for (int t = 0; t < 16; t++) {
            int tt = layer * 16 + t;
            __syncthreads();   // prev compute / act writes done
            storeB();
            __syncthreads();
            if (tt + 1 < 48) loadB(tt + 1);    // prefetch under compute

            unsigned aH[2][4];
#pragma unroll
            for (int mf = 0; mf < 2; mf++) {
                uint32_t ra = su + (uint32_t)(wm * 32 + mf * 16 + (int)lrow) * AC_STRIDE +
                              (uint32_t)t * 32u + lseg;
                ldm4(aH[mf][0], aH[mf][1], aH[mf][2], aH[mf][3], ra);
            }
#pragma unroll
            for (int np = 0; np < 4; np++) {
                uint32_t rb = su + MB_BH + (uint32_t)(wn * 64 + np * 16) * 48u +
                              brow * 48u + bkoff;
                unsigned bh0, bh1, bh2, bh3, bl0, bl1, bl2, bl3;
                ldm4(bh0, bh1, bh2, bh3, rb);
                ldm4(bl0, bl1, bl2, bl3, rb + (MB_BL - MB_BH));
                int nf0 = np * 2, nf1 = np * 2 + 1;
#pragma unroll
                for (int mf = 0; mf < 2; mf++) mma_f16(acc[mf][nf0], aH[mf], bh0, bh1);
#pragma unroll
                for (int mf = 0; mf < 2; mf++) mma_f16(acc[mf][nf1], aH[mf], bh2, bh3);
#pragma unroll
                for (int mf = 0; mf < 2; mf++) mma_f16(acc[mf][nf0], aH[mf], bl0, bl1);
#pragma unroll
                for (int mf = 0; mf < 2; mf++) mma_f16(acc[mf][nf1], aH[mf], bl2, bl3);
            }
        }
        __syncthreads();   // all A reads done before overwriting act plane

        if (layer < 2) {
#pragma unroll
            for (int nf = 0; nf < 8; nf++) {
                int col = wn * 64 + nf * 8 + tg * 2;
                float bv0 = bias[col], bv1 = bias[col + 1];
#pragma unroll
                for (int mf = 0; mf < 2; mf++) {
                    int r0 = wm * 32 + mf * 16 + g;
                    float v00 = fmaxf(acc[mf][nf][0] + bv0, 0.0f);
                    float v01 = fmaxf(acc[mf][nf][1] + bv1, 0.0f);
                    float v10 = fmaxf(acc[mf][nf][2] + bv0, 0.0f);
                    float v11 = fmaxf(acc[mf][nf][3] + bv1, 0.0f);
                    uint32_t o0 = (uint32_t)r0 * AC_STRIDE + (uint32_t)col * 2u;
                    uint32_t o1 = (uint32_t)(r0 + 8) * AC_STRIDE + (uint32_t)col * 2u;
                    *(uint32_t*)(smem + o0) = (uint32_t)f2h(v00) | ((uint32_t)f2h(v01) << 16);
                    *(uint32_t*)(smem + o1) = (uint32_t)f2h(v10) | ((uint32_t)f2h(v11) << 16);
                }
            }
        }
    }

    // ---- projection epilogue (layer3 acc): wp = rwt * relu(acc+b3)·w4 ----
    float* sred = (float*)(smem + MB_BH);          // [4][64][3] = 3KB (B buffer reuse)
    float* w4s  = (float*)(smem + MB_BH + 3072);   // 768 floats
    for (int i = tid; i < HID * 3; i += 256) w4s[i] = w4[i];
    __syncthreads();
    float s[4][3];
#pragma unroll
    for (int i = 0; i < 4; i++) { s[i][0] = 0.f; s[i][1] = 0.f; s[i][2] = 0.f; }
#pragma unroll
    for (int nf = 0; nf < 8; nf++) {
        int col = wn * 64 + nf * 8 + tg * 2;
        float bv0 = b3[col], bv1 = b3[col + 1];
        float w00 = w4s[col * 3 + 0], w01 = w4s[col * 3 + 1], w02 = w4s[col * 3 + 2];
        float w10 = w4s[col * 3 + 3], w11 = w4s[col * 3 + 4], w12 = w4s[col * 3 + 5];
#pragma unroll
        for (int mf = 0; mf < 2; mf++) {
            float v00 = fmaxf(acc[mf][nf][0] + bv0, 0.0f);
            float v01 = fmaxf(acc[mf][nf][1] + bv1, 0.0f);
            float v10 = fmaxf(acc[mf][nf][2] + bv0, 0.0f);
            float v11 = fmaxf(acc[mf][nf][3] + bv1, 0.0f);
            int i0 = mf * 2, i1 = mf * 2 + 1;
            s[i0][0] += v00 * w00 + v01 * w10;
            s[i0][1] += v00 * w01 + v01 * w11;
            s[i0][2] += v00 * w02 + v01 * w12;
            s[i1][0] += v10 * w00 + v11 * w10;
            s[i1][1] += v10 * w01 + v11 * w11;
            s[i1][2] += v10 * w02 + v11 * w12;
        }
    }
#pragma unroll
    for (int i = 0; i < 4; i++)
#pragma unroll
        for (int c = 0; c < 3; c++) {
            s[i][c] += __shfl_xor_sync(0xffffffffu, s[i][c], 1);
            s[i][c] += __shfl_xor_sync(0xffffffffu, s[i][c], 2);
        }
    if (tg == 0) {
#pragma unroll
        for (int mf = 0; mf < 2; mf++)
#pragma unroll
            for (int hh = 0; hh < 2; hh++) {
                int row = wm * 32 + mf * 16 + g + hh * 8;
                int i = mf * 2 + hh;
                sred[(wn * 64 + row) * 3 + 0] = s[i][0];
                sred[(wn * 64 + row) * 3 + 1] = s[i][1];
                sred[(wn * 64 + row) * 3 + 2] = s[i][2];
            }
    }
    __syncthreads();
    for (int i = tid; i < 64 * 3; i += 256) {
        int row = i / 3, c = i % 3;
        float sum = sred[(0 * 64 + row) * 3 + c] + sred[(1 * 64 + row) * 3 + c]
                  + sred[(2 * 64 + row) * 3 + c] + sred[(3 * 64 + row) * 3 + c];
        WP[(size_t)(m0 + row) * 3 + c] = g_rwt[m0 + row] * sum;
    }
}

// ---------------- combine ----------------
__global__ void k_comb(const float* __restrict__ wp, const float* __restrict__ b4,
                       float* __restrict__ out) {
    int q = blockIdx.x * blockDim.x + threadIdx.x;
    if (q >= BQ * NQ) return;
    int pg = g_qpc[q];
    float b40 = b4[0], b41 = b4[1], b42 = b4[2];
    float pa0 = 0.f, pa1 = 0.f, pa2 = 0.f, pl0 = 0.f, pl1 = 0.f, pl2 = 0.f;
#pragma unroll
    for (int k = 0; k < 4; k++) {
        size_t ra = (size_t)(pg * 4 + k) * 3;
        pa0 += wp[ra + 0]; pa1 += wp[ra + 1]; pa2 += wp[ra + 2];
        size_t rl = (size_t)(ATTR + q * 4 + k) * 3;
        pl0 += wp[rl + 0]; pl1 += wp[rl + 1]; pl2 += wp[rl + 2];
    }
    out[(size_t)q * 3 + 0] = 0.5f * (pa0 + b40) + 0.5f * (pl0 + b40);
    out[(size_t)q * 3 + 1] = 0.5f * (pa1 + b41) + 0.5f * (pl1 + b41);
    out[(size_t)q * 3 + 2] = 0.5f * (pa2 + b42) + 0.5f * (pl2 + b42);
}

// ---------------- launch ----------------
extern "C" void kernel_launch(void* const* d_in, const int* in_sizes, int n_in,
                              void* d_out, int out_size) {
    const float* feat  = (const float*)d_in[0];
    const float* attn  = (const float*)d_in[1];
    const float* coord = (const float*)d_in[2];
    const float* cell  = (const float*)d_in[3];
    const float* w0 = (const float*)d_in[4];
    const float* b0 = (const float*)d_in[5];
    const float* w1 = (const float*)d_in[6];
    const float* b1 = (const float*)d_in[7];
    const float* w2 = (const float*)d_in[8];
    const float* b2 = (const float*)d_in[9];
    const float* w3 = (const float*)d_in[10];
    const float* b3 = (const float*)d_in[11];
    const float* w4 = (const float*)d_in[12];
    const float* b4 = (const float*)d_in[13];
    float* out = (float*)d_out;

    float *Tt, *WP;
    cudaGetSymbolAddress((void**)&Tt, g_T);
    cudaGetSymbolAddress((void**)&WP, g_wp);
    const float* w0tail = w0 + (size_t)D9 * HID;

    static int once = 0;
    static cudaStream_t s2;
    static cudaEvent_t evF, evJ;
    if (!once) {
        cudaFuncSetAttribute(k_tgemm, cudaFuncAttributeMaxDynamicSharedMemorySize, TG_TOT);
        cudaFuncSetAttribute(k_mlp,   cudaFuncAttributeMaxDynamicSharedMemorySize, MSM_TOT);
        cudaStreamCreateWithFlags(&s2, cudaStreamNonBlocking);
        cudaEventCreateWithFlags(&evF, cudaEventDisableTiming);
        cudaEventCreateWithFlags(&evJ, cudaEventDisableTiming);
        once = 1;
    }

    // fork: top-k / build chain on s2, weight-prep + T-gemm on main stream
    cudaEventRecord(evF, 0);
    cudaStreamWaitEvent(s2, evF, 0);
    k_argmax<<<(BQ * HWQ + 255) / 256, 256, 0, s2>>>(attn);
    k_top4a<<<BQ * NCHUNK, 256, 0, s2>>>(attn);
    k_top4b<<<1, 256, 0, s2>>>();
    k_build<<<(BQ * HWQ + BQ * NQ + 255) / 256, 256, 0, s2>>>(coord, cell);
    cudaEventRecord(evJ, s2);

    int prepn = 36 * 2048 + 3 * 32768;
    k_prepw<<<(prepn + 255) / 256, 256>>>(w0, w1, w2, w3);
    k_tgemm<<<NPIX / 64, 256, TG_TOT>>>(feat, b0, Tt);

    cudaStreamWaitEvent(0, evJ, 0);   // join before fused MLP
    k_mlp<<<NR2 / 64, 256, MSM_TOT>>>(Tt, b1, b2, b3, w0tail, w4, WP);

    k_comb<<<(BQ * NQ + 255) / 256, 256>>>(WP, b4, out);
}